// round 1
// baseline (speedup 1.0000x reference)
#include <cuda_runtime.h>
#include <cstdint>
#include <cstdio>

#define BATCH 8192

// ---------------- scratch (static device allocations; no cudaMalloc) ----------------
__device__ float  g_y0[(size_t)BATCH * 196 * 128];   // [b][14][14][khw(4)][c(32)]  822MB
__device__ float  g_y1[(size_t)BATCH * 49 * 256];    // [b][7][7][khw(4)][c(64)]    411MB
__device__ float  g_y2[(size_t)BATCH * 49 * 128];    // [b][49][c(128)]             206MB
__device__ double g_stats[448];                      // L0: sum 0..31, sq 32..63 | L1: 64..127,128..191 | L2: 192..319,320..447
__device__ float  g_s0[32], g_t0[32], g_s1[64], g_t1[64], g_s2[128], g_t2[128];
__device__ float  g_B1[128 * 64];                    // [k=khw*32+c][oc]
__device__ float  g_B2[256 * 128];                   // [k=khw*64+c][oc]

// ---------------- f32x2 helpers ----------------
__device__ __forceinline__ unsigned long long dup2(float a) {
    unsigned long long r;
    asm("mov.b64 %0, {%1, %1};" : "=l"(r) : "f"(a));
    return r;
}
__device__ __forceinline__ void fma2(unsigned long long& c, unsigned long long a, unsigned long long b) {
    asm("fma.rn.f32x2 %0, %1, %2, %0;" : "+l"(c) : "l"(a), "l"(b));
}
__device__ __forceinline__ float2 unpk(unsigned long long v) {
    float2 f;
    asm("mov.b64 {%0, %1}, %2;" : "=f"(f.x), "=f"(f.y) : "l"(v));
    return f;
}

// ---------------- prep: zero stats, reorganize weights into GEMM-B layout ----------------
__global__ void prep_k(const float* __restrict__ w1, const float* __restrict__ w2) {
    int stride = blockDim.x * gridDim.x;
    int t0 = blockIdx.x * blockDim.x + threadIdx.x;
    for (int i = t0; i < 448; i += stride) g_stats[i] = 0.0;
    for (int i = t0; i < 128 * 64; i += stride) {
        int k = i >> 6, oc = i & 63;
        int khw = k >> 5, c = k & 31, di = khw >> 1, dj = khw & 1;
        g_B1[i] = w1[((oc * 32 + c) * 2 + di) * 2 + dj];
    }
    for (int i = t0; i < 256 * 128; i += stride) {
        int k = i >> 7, oc = i & 127;
        int khw = k >> 6, c = k & 63, di = khw >> 1, dj = khw & 1;
        g_B2[i] = w2[((oc * 64 + c) * 2 + di) * 2 + dj];
    }
}

// ---------------- conv0: 1->32, 3x3 SAME. Raw output (no bias: BN cancels it) + stats ----------------
__global__ void __launch_bounds__(256) conv0_k(const float* __restrict__ x, const float* __restrict__ w0) {
    __shared__ float sx[900];           // 30x30 zero-padded image
    __shared__ float rs[256], rq[256];
    int b = blockIdx.x, tid = threadIdx.x;
    for (int i = tid; i < 900; i += 256) sx[i] = 0.f;
    __syncthreads();
    const float* xb = x + (size_t)b * 784;
    for (int i = tid; i < 784; i += 256) {
        int r = i / 28, c = i - r * 28;
        sx[(r + 1) * 30 + c + 1] = xb[i];
    }
    __syncthreads();
    int c = tid & 31;      // channel (lane)
    int p = tid >> 5;      // warp id -> pixel phase
    float w[9];
#pragma unroll
    for (int i = 0; i < 9; i++) w[i] = w0[c * 9 + i];
    float sum = 0.f, sq = 0.f;
    float* outb = g_y0 + (size_t)b * (196 * 128);
    for (int it = 0; it < 98; it++) {
        int pix = it * 8 + p;
        int OH = pix / 28, OW = pix - OH * 28;
        const float* s = &sx[OH * 30 + OW];
        float acc = w[0] * s[0];
        acc = fmaf(w[1], s[1], acc);  acc = fmaf(w[2], s[2], acc);
        acc = fmaf(w[3], s[30], acc); acc = fmaf(w[4], s[31], acc); acc = fmaf(w[5], s[32], acc);
        acc = fmaf(w[6], s[60], acc); acc = fmaf(w[7], s[61], acc); acc = fmaf(w[8], s[62], acc);
        int oh = OH >> 1, ow = OW >> 1, khw = ((OH & 1) << 1) | (OW & 1);
        outb[(size_t)((oh * 14 + ow) * 4 + khw) * 32 + c] = acc;
        sum += acc;
        sq = fmaf(acc, acc, sq);
    }
    rs[tid] = sum; rq[tid] = sq;
    __syncthreads();
    if (p == 0) {
        float S = 0.f, Q = 0.f;
#pragma unroll
        for (int j = 0; j < 8; j++) { S += rs[j * 32 + c]; Q += rq[j * 32 + c]; }
        atomicAdd(&g_stats[c], (double)S);
        atomicAdd(&g_stats[32 + c], (double)Q);
    }
}

// ---------------- scale kernels: stats -> (scale, shift) per channel ----------------
__global__ void scale0_k(const float* __restrict__ g, const float* __restrict__ be) {
    int c = threadIdx.x;  // 32
    const double invN = 1.0 / 6422528.0;
    double mean = g_stats[c] * invN;
    double var  = g_stats[32 + c] * invN - mean * mean;
    double s = (double)g[c] / sqrt(var + 1e-5);
    g_s0[c] = (float)s;
    g_t0[c] = (float)((double)be[c] - mean * s);
}
__global__ void scale1_k(const float* __restrict__ g, const float* __restrict__ be) {
    int c = threadIdx.x;  // 64
    const double invN = 1.0 / 1605632.0;
    double mean = g_stats[64 + c] * invN;
    double var  = g_stats[128 + c] * invN - mean * mean;
    double s = (double)g[c] / sqrt(var + 1e-5);
    g_s1[c] = (float)s;
    g_t1[c] = (float)((double)be[c] - mean * s);
}
__global__ void scale2_k(const float* __restrict__ g, const float* __restrict__ be) {
    int c = threadIdx.x;  // 128
    const double invN = 1.0 / 401408.0;
    double mean = g_stats[192 + c] * invN;
    double var  = g_stats[320 + c] * invN - mean * mean;
    double s = (double)g[c] / sqrt(var + 1e-5);
    g_s2[c] = (float)s;
    g_t2[c] = (float)((double)be[c] - mean * s);
}

// ---------------- conv1 as GEMM: M=1605632, K=128, N=64. BN0+ReLU folded into A-load ----------------
// Tile: BM=128, BN=64(all), BK=128(all). 256 thr: TM=8 (rows mt+16i), TN=4 (pairs via f32x2)
#define SMEM1_FLOATS (128 * 132 + 8192 + 32 + 32 + 64 + 64)
__global__ void __launch_bounds__(256, 2) conv1_k() {
    extern __shared__ float sm[];
    float* As    = sm;                  // [m(128)][k(128)] pad->132
    float* Bs    = As + 128 * 132;      // [k(128)][n(64)]
    float* ssc   = Bs + 8192;           // 32
    float* ssh   = ssc + 32;            // 32
    float* s_sum = ssh + 32;            // 64
    float* s_sq  = s_sum + 64;          // 64
    int tid = threadIdx.x;
    if (tid < 32) { ssc[tid] = g_s0[tid]; ssh[tid] = g_t0[tid]; }
    if (tid < 64) { s_sum[tid] = 0.f; s_sq[tid] = 0.f; }
#pragma unroll
    for (int i = tid; i < 2048; i += 256) ((float4*)Bs)[i] = ((const float4*)g_B1)[i];
    __syncthreads();
    size_t m0 = (size_t)blockIdx.x * 128;
    const float* Ag = g_y0 + m0 * 128;
    {
        int k4 = tid & 31, r00 = tid >> 5;
#pragma unroll
        for (int rr = 0; rr < 16; rr++) {
            int r = r00 + rr * 8;
            float4 v = ((const float4*)(Ag + (size_t)r * 128))[k4];
            int c = (k4 << 2) & 31;
            v.x = fmaxf(fmaf(v.x, ssc[c + 0], ssh[c + 0]), 0.f);
            v.y = fmaxf(fmaf(v.y, ssc[c + 1], ssh[c + 1]), 0.f);
            v.z = fmaxf(fmaf(v.z, ssc[c + 2], ssh[c + 2]), 0.f);
            v.w = fmaxf(fmaf(v.w, ssc[c + 3], ssh[c + 3]), 0.f);
            ((float4*)(As + r * 132))[k4] = v;
        }
    }
    __syncthreads();
    int mt = tid >> 4, nt = tid & 15;
    unsigned long long acc[8][2];
#pragma unroll
    for (int i = 0; i < 8; i++) { acc[i][0] = 0ull; acc[i][1] = 0ull; }
    const float* Aw = As + mt * 132;
#pragma unroll 4
    for (int k = 0; k < 128; k++) {
        ulonglong2 b = *(const ulonglong2*)(Bs + (k << 6) + (nt << 2));
#pragma unroll
        for (int i = 0; i < 8; i++) {
            unsigned long long a2 = dup2(Aw[i * 16 * 132 + k]);
            fma2(acc[i][0], a2, b.x);
            fma2(acc[i][1], a2, b.y);
        }
    }
    float csum[4] = {0, 0, 0, 0}, csq[4] = {0, 0, 0, 0};
#pragma unroll
    for (int i = 0; i < 8; i++) {
        float2 p0 = unpk(acc[i][0]), p1 = unpk(acc[i][1]);
        size_t mm = m0 + mt + i * 16;
        int bb  = (int)(mm / 196);
        int rem = (int)(mm - (size_t)bb * 196);
        int OH = rem / 14, OW = rem - OH * 14;
        size_t addr = (((size_t)bb * 7 + (OH >> 1)) * 7 + (OW >> 1)) * 256 +
                      ((((OH & 1) << 1) | (OW & 1)) << 6) + (nt << 2);
        *(float4*)(g_y1 + addr) = make_float4(p0.x, p0.y, p1.x, p1.y);
        csum[0] += p0.x; csq[0] = fmaf(p0.x, p0.x, csq[0]);
        csum[1] += p0.y; csq[1] = fmaf(p0.y, p0.y, csq[1]);
        csum[2] += p1.x; csq[2] = fmaf(p1.x, p1.x, csq[2]);
        csum[3] += p1.y; csq[3] = fmaf(p1.y, p1.y, csq[3]);
    }
#pragma unroll
    for (int j = 0; j < 4; j++) {
        atomicAdd(&s_sum[(nt << 2) + j], csum[j]);
        atomicAdd(&s_sq[(nt << 2) + j], csq[j]);
    }
    __syncthreads();
    if (tid < 64) {
        atomicAdd(&g_stats[64 + tid], (double)s_sum[tid]);
        atomicAdd(&g_stats[128 + tid], (double)s_sq[tid]);
    }
}

// ---------------- conv2 as GEMM: M=401408, K=256, N=128. BN1+ReLU folded into A-load ----------------
// Tile: BM=128, BN=128(all), BK=64 x 4 chunks. 256 thr: TM=8, TN=8 (two groups of 4 cols: nt*4 and 64+nt*4)
#define SMEM2_FLOATS (128 * 68 + 8192 + 64 + 64 + 128 + 128)
__global__ void __launch_bounds__(256, 2) conv2_k() {
    extern __shared__ float sm[];
    float* As    = sm;                 // [m(128)][k(64)] pad->68
    float* Bs    = As + 128 * 68;      // [k(64)][n(128)]
    float* ssc   = Bs + 8192;          // 64
    float* ssh   = ssc + 64;           // 64
    float* s_sum = ssh + 64;           // 128
    float* s_sq  = s_sum + 128;        // 128
    int tid = threadIdx.x;
    if (tid < 64)  { ssc[tid] = g_s1[tid]; ssh[tid] = g_t1[tid]; }
    if (tid < 128) { s_sum[tid] = 0.f; s_sq[tid] = 0.f; }
    size_t m0 = (size_t)blockIdx.x * 128;
    const float* Ag = g_y1 + m0 * 256;
    int mt = tid >> 4, nt = tid & 15;
    int k16 = tid & 15, r00 = tid >> 4;
    unsigned long long acc[8][4];
#pragma unroll
    for (int i = 0; i < 8; i++)
#pragma unroll
        for (int j = 0; j < 4; j++) acc[i][j] = 0ull;
    for (int kc = 0; kc < 4; kc++) {
        __syncthreads();
        const float4* Bg = (const float4*)(g_B2 + kc * 8192);
#pragma unroll
        for (int i = tid; i < 2048; i += 256) ((float4*)Bs)[i] = Bg[i];
#pragma unroll
        for (int rr = 0; rr < 8; rr++) {
            int r = r00 + rr * 16;
            float4 v = *(const float4*)(Ag + (size_t)r * 256 + kc * 64 + (k16 << 2));
            int c = k16 << 2;
            v.x = fmaxf(fmaf(v.x, ssc[c + 0], ssh[c + 0]), 0.f);
            v.y = fmaxf(fmaf(v.y, ssc[c + 1], ssh[c + 1]), 0.f);
            v.z = fmaxf(fmaf(v.z, ssc[c + 2], ssh[c + 2]), 0.f);
            v.w = fmaxf(fmaf(v.w, ssc[c + 3], ssh[c + 3]), 0.f);
            ((float4*)(As + r * 68))[k16] = v;
        }
        __syncthreads();
        const float* Aw = As + mt * 68;
#pragma unroll 4
        for (int k = 0; k < 64; k++) {
            ulonglong2 b0 = *(const ulonglong2*)(Bs + (k << 7) + (nt << 2));
            ulonglong2 b1 = *(const ulonglong2*)(Bs + (k << 7) + 64 + (nt << 2));
#pragma unroll
            for (int i = 0; i < 8; i++) {
                unsigned long long a2 = dup2(Aw[i * 16 * 68 + k]);
                fma2(acc[i][0], a2, b0.x);
                fma2(acc[i][1], a2, b0.y);
                fma2(acc[i][2], a2, b1.x);
                fma2(acc[i][3], a2, b1.y);
            }
        }
    }
    float csum[8] = {0, 0, 0, 0, 0, 0, 0, 0}, csq[8] = {0, 0, 0, 0, 0, 0, 0, 0};
#pragma unroll
    for (int i = 0; i < 8; i++) {
        float2 p0 = unpk(acc[i][0]), p1 = unpk(acc[i][1]);
        float2 p2 = unpk(acc[i][2]), p3 = unpk(acc[i][3]);
        size_t mm = m0 + mt + i * 16;          // = (b*7+oh)*7+ow (row-major y2)
        float* dst = g_y2 + mm * 128;
        *(float4*)(dst + (nt << 2))      = make_float4(p0.x, p0.y, p1.x, p1.y);
        *(float4*)(dst + 64 + (nt << 2)) = make_float4(p2.x, p2.y, p3.x, p3.y);
        csum[0] += p0.x; csq[0] = fmaf(p0.x, p0.x, csq[0]);
        csum[1] += p0.y; csq[1] = fmaf(p0.y, p0.y, csq[1]);
        csum[2] += p1.x; csq[2] = fmaf(p1.x, p1.x, csq[2]);
        csum[3] += p1.y; csq[3] = fmaf(p1.y, p1.y, csq[3]);
        csum[4] += p2.x; csq[4] = fmaf(p2.x, p2.x, csq[4]);
        csum[5] += p2.y; csq[5] = fmaf(p2.y, p2.y, csq[5]);
        csum[6] += p3.x; csq[6] = fmaf(p3.x, p3.x, csq[6]);
        csum[7] += p3.y; csq[7] = fmaf(p3.y, p3.y, csq[7]);
    }
#pragma unroll
    for (int j = 0; j < 4; j++) {
        atomicAdd(&s_sum[(nt << 2) + j], csum[j]);
        atomicAdd(&s_sq[(nt << 2) + j], csq[j]);
        atomicAdd(&s_sum[64 + (nt << 2) + j], csum[4 + j]);
        atomicAdd(&s_sq[64 + (nt << 2) + j], csq[4 + j]);
    }
    __syncthreads();
    if (tid < 128) {
        atomicAdd(&g_stats[192 + tid], (double)s_sum[tid]);
        atomicAdd(&g_stats[320 + tid], (double)s_sq[tid]);
    }
}

// ---------------- final: BN2+ReLU fold, avg-pool over 49, FC 128->10 ----------------
__global__ void __launch_bounds__(128) final_k(const float* __restrict__ wfc,
                                               const float* __restrict__ bfc,
                                               float* __restrict__ out) {
    __shared__ float f[128];
    int b = blockIdx.x, tid = threadIdx.x;
    const float* y = g_y2 + (size_t)b * 49 * 128;
    float s = g_s2[tid], t = g_t2[tid];
    float acc = 0.f;
#pragma unroll 7
    for (int p = 0; p < 49; p++) acc += fmaxf(fmaf(y[p * 128 + tid], s, t), 0.f);
    f[tid] = acc * (1.f / 49.f);
    __syncthreads();
    if (tid < 10) {
        float o = bfc[tid];
        const float* wr = wfc + tid * 128;
#pragma unroll 8
        for (int c2 = 0; c2 < 128; c2++) o = fmaf(f[c2], wr[c2], o);
        out[(size_t)b * 10 + tid] = o;
    }
}

// ---------------- launch ----------------
extern "C" void kernel_launch(void* const* d_in, const int* in_sizes, int n_in,
                              void* d_out, int out_size) {
    const float* x   = (const float*)d_in[0];
    const float* w0  = (const float*)d_in[1];
    // d_in[2] = b0 (unused: cancelled by BN)
    const float* g0  = (const float*)d_in[3];
    const float* be0 = (const float*)d_in[4];
    const float* w1  = (const float*)d_in[5];
    // d_in[6] = b1 unused
    const float* g1  = (const float*)d_in[7];
    const float* be1 = (const float*)d_in[8];
    const float* w2  = (const float*)d_in[9];
    // d_in[10] = b2 unused
    const float* g2  = (const float*)d_in[11];
    const float* be2 = (const float*)d_in[12];
    const float* wfc = (const float*)d_in[13];
    const float* bfc = (const float*)d_in[14];
    float* out = (float*)d_out;

    cudaFuncSetAttribute(conv1_k, cudaFuncAttributeMaxDynamicSharedMemorySize, SMEM1_FLOATS * 4);
    cudaFuncSetAttribute(conv2_k, cudaFuncAttributeMaxDynamicSharedMemorySize, SMEM2_FLOATS * 4);

    prep_k<<<64, 256>>>(w1, w2);
    conv0_k<<<BATCH, 256>>>(x, w0);
    scale0_k<<<1, 32>>>(g0, be0);
    conv1_k<<<12544, 256, SMEM1_FLOATS * 4>>>();
    scale1_k<<<1, 64>>>(g1, be1);
    conv2_k<<<3136, 256, SMEM2_FLOATS * 4>>>();
    scale2_k<<<1, 128>>>(g2, be2);
    final_k<<<BATCH, 128>>>(wfc, bfc, out);
}

// round 6
// speedup vs baseline: 2.2569x; 2.2569x over previous
#include <cuda_runtime.h>
#include <cuda_fp16.h>
#include <cstdint>

#define BATCH 8192

// ---------------- scratch ----------------
__device__ __align__(16) __half g_y0h[(size_t)BATCH * 196 * 128];   // [b][14][14][khw(4)][c(32)] raw conv0
__device__ __align__(16) __half g_y1h[(size_t)BATCH * 49 * 256];    // [b][7][7][khw(4)][c(64)]   raw conv1
__device__ __align__(16) __half g_y2h[(size_t)BATCH * 49 * 128];    // [b][49][c(128)]            raw conv2
__device__ double g_stats[448];
__device__ float  g_s0[32], g_t0[32], g_s1[64], g_t1[64], g_s2[128], g_t2[128];
// B operands, [n][k] row-major (B^T), hi/lo fp16 split
__device__ __align__(16) __half g_B1hi[64 * 128],  g_B1lo[64 * 128];
__device__ __align__(16) __half g_B2hi[128 * 256], g_B2lo[128 * 256];

// ---------------- warp-mma helpers (sm_80-era: legal on base sm_103 target) ----------------
__device__ __forceinline__ uint32_t s2u(const void* p) {
    uint32_t a;
    asm("{ .reg .u64 t; cvta.to.shared.u64 t, %1; cvt.u32.u64 %0, t; }" : "=r"(a) : "l"(p));
    return a;
}
__device__ __forceinline__ void ldm4(uint32_t* r, uint32_t addr) {
    asm volatile("ldmatrix.sync.aligned.m8n8.x4.shared.b16 {%0,%1,%2,%3}, [%4];"
                 : "=r"(r[0]), "=r"(r[1]), "=r"(r[2]), "=r"(r[3]) : "r"(addr));
}
__device__ __forceinline__ void mmaf16(float* d, const uint32_t* a, uint32_t b0, uint32_t b1) {
    asm volatile("mma.sync.aligned.m16n8k16.row.col.f32.f16.f16.f32 "
                 "{%0,%1,%2,%3}, {%4,%5,%6,%7}, {%8,%9}, {%0,%1,%2,%3};"
                 : "+f"(d[0]), "+f"(d[1]), "+f"(d[2]), "+f"(d[3])
                 : "r"(a[0]), "r"(a[1]), "r"(a[2]), "r"(a[3]), "r"(b0), "r"(b1));
}
__device__ __forceinline__ void red4(float& v) {   // sum over lanes sharing (lane&3)
    v += __shfl_xor_sync(0xFFFFFFFFu, v, 4);
    v += __shfl_xor_sync(0xFFFFFFFFu, v, 8);
    v += __shfl_xor_sync(0xFFFFFFFFu, v, 16);
}

// ---------------- prep: zero stats, B^T hi/lo weights ----------------
__global__ void prep_k(const float* __restrict__ w1, const float* __restrict__ w2) {
    int t0 = blockIdx.x * blockDim.x + threadIdx.x, stride = blockDim.x * gridDim.x;
    for (int i = t0; i < 448; i += stride) g_stats[i] = 0.0;
    for (int i = t0; i < 8192; i += stride) {          // B1: [oc=64][k=khw*32+c]
        int r = i >> 7, k = i & 127, khw = k >> 5, c = k & 31;
        float w = w1[((r * 32 + c) * 2 + (khw >> 1)) * 2 + (khw & 1)];
        __half hi = __float2half_rn(w);
        g_B1hi[i] = hi;
        g_B1lo[i] = __float2half_rn(w - __half2float(hi));
    }
    for (int i = t0; i < 32768; i += stride) {         // B2: [oc=128][k=khw*64+c]
        int r = i >> 8, k = i & 255, khw = k >> 6, c = k & 63;
        float w = w2[((r * 64 + c) * 2 + (khw >> 1)) * 2 + (khw & 1)];
        __half hi = __float2half_rn(w);
        g_B2hi[i] = hi;
        g_B2lo[i] = __float2half_rn(w - __half2float(hi));
    }
}

// ---------------- conv0: 1->32, 3x3 SAME, raw fp16 output + exact fp32 stats ----------------
__global__ void __launch_bounds__(256) conv0_k(const float* __restrict__ x, const float* __restrict__ w0) {
    __shared__ float sx[900];
    __shared__ float rs[256], rq[256];
    int b = blockIdx.x, tid = threadIdx.x;
    for (int i = tid; i < 900; i += 256) sx[i] = 0.f;
    __syncthreads();
    const float* xb = x + (size_t)b * 784;
    for (int i = tid; i < 784; i += 256) {
        int r = i / 28, c = i - r * 28;
        sx[(r + 1) * 30 + c + 1] = xb[i];
    }
    __syncthreads();
    int c = tid & 31, p = tid >> 5;
    float w[9];
#pragma unroll
    for (int i = 0; i < 9; i++) w[i] = w0[c * 9 + i];
    float sum = 0.f, sq = 0.f;
    __half* outb = g_y0h + (size_t)b * (196 * 128);
    for (int it = 0; it < 98; it++) {
        int pix = it * 8 + p;
        int OH = pix / 28, OW = pix - OH * 28;
        const float* s = &sx[OH * 30 + OW];
        float acc = w[0] * s[0];
        acc = fmaf(w[1], s[1], acc);  acc = fmaf(w[2], s[2], acc);
        acc = fmaf(w[3], s[30], acc); acc = fmaf(w[4], s[31], acc); acc = fmaf(w[5], s[32], acc);
        acc = fmaf(w[6], s[60], acc); acc = fmaf(w[7], s[61], acc); acc = fmaf(w[8], s[62], acc);
        int oh = OH >> 1, ow = OW >> 1, khw = ((OH & 1) << 1) | (OW & 1);
        outb[(size_t)((oh * 14 + ow) * 4 + khw) * 32 + c] = __float2half_rn(acc);
        sum += acc;
        sq = fmaf(acc, acc, sq);
    }
    rs[tid] = sum; rq[tid] = sq;
    __syncthreads();
    if (p == 0) {
        float S = 0.f, Q = 0.f;
#pragma unroll
        for (int j = 0; j < 8; j++) { S += rs[j * 32 + c]; Q += rq[j * 32 + c]; }
        atomicAdd(&g_stats[c], (double)S);
        atomicAdd(&g_stats[32 + c], (double)Q);
    }
}

// ---------------- scale kernels ----------------
__global__ void scale0_k(const float* __restrict__ g, const float* __restrict__ be) {
    int c = threadIdx.x;
    const double invN = 1.0 / 6422528.0;
    double mean = g_stats[c] * invN;
    double var  = g_stats[32 + c] * invN - mean * mean;
    double s = (double)g[c] / sqrt(var + 1e-5);
    g_s0[c] = (float)s; g_t0[c] = (float)((double)be[c] - mean * s);
}
__global__ void scale1_k(const float* __restrict__ g, const float* __restrict__ be) {
    int c = threadIdx.x;
    const double invN = 1.0 / 1605632.0;
    double mean = g_stats[64 + c] * invN;
    double var  = g_stats[128 + c] * invN - mean * mean;
    double s = (double)g[c] / sqrt(var + 1e-5);
    g_s1[c] = (float)s; g_t1[c] = (float)((double)be[c] - mean * s);
}
__global__ void scale2_k(const float* __restrict__ g, const float* __restrict__ be) {
    int c = threadIdx.x;
    const double invN = 1.0 / 401408.0;
    double mean = g_stats[192 + c] * invN;
    double var  = g_stats[320 + c] * invN - mean * mean;
    double s = (double)g[c] / sqrt(var + 1e-5);
    g_s2[c] = (float)s; g_t2[c] = (float)((double)be[c] - mean * s);
}

// ======================= conv1: HMMA GEMM  M=1605632(x128), N=64, K=128 =======================
// smem halves, stride 136 (272B: rows hit distinct banks for ldmatrix)
// A [128][136] @0 (34816B) | Bhi [64][136] @34816 (17408B) | Blo @52224 | ssc@69632 ssh@69760 | s_sum@69888 (128 f)
#define A1STR 136
#define SM1_BH 34816
#define SM1_BL 52224
#define SM1_BYTES 70400

__global__ void __launch_bounds__(256) conv1_k() {
    extern __shared__ __align__(16) char sm[];
    uint32_t sb = s2u(sm);
    float* ssc   = (float*)(sm + 69632);
    float* ssh   = (float*)(sm + 69760);
    float* s_sum = (float*)(sm + 69888);   // 64 sum | 64 sq
    int tid = threadIdx.x, wid = tid >> 5, lid = tid & 31;
    if (tid < 32) { ssc[tid] = g_s0[tid]; ssh[tid] = g_t0[tid]; }
    if (tid < 128) s_sum[tid] = 0.f;
    {
        const uint4* s1 = (const uint4*)g_B1hi;
        const uint4* s2 = (const uint4*)g_B1lo;
        for (int i = tid; i < 1024; i += 256) {
            int r = i >> 4, c = i & 15;
            *(uint4*)(sm + SM1_BH + (r * A1STR + c * 8) * 2) = s1[i];
            *(uint4*)(sm + SM1_BL + (r * A1STR + c * 8) * 2) = s2[i];
        }
    }
    size_t m0 = (size_t)blockIdx.x * 128;
    {   // A tile: BN0+ReLU folded, fp16
        int r = tid >> 1, h = tid & 1;
        const uint4* src = (const uint4*)(g_y0h + (m0 + r) * 128 + h * 64);
#pragma unroll
        for (int i = 0; i < 8; i++) {
            uint4 v = src[i];
            int k0 = h * 64 + i * 8;
            __half2* hp = (__half2*)&v;
#pragma unroll
            for (int j = 0; j < 4; j++) {
                int c = (k0 + 2 * j) & 31;
                float2 f = __half22float2(hp[j]);
                f.x = fmaxf(fmaf(f.x, ssc[c], ssh[c]), 0.f);
                f.y = fmaxf(fmaf(f.y, ssc[c + 1], ssh[c + 1]), 0.f);
                hp[j] = __float22half2_rn(f);
            }
            *(uint4*)(sm + (r * A1STR + k0) * 2) = v;
        }
    }
    __syncthreads();

    int wr = wid & 3, wc = wid >> 2;           // warp grid 4(m) x 2(n)
    int mb = wr * 32, nb = wc * 32;
    float acc[2][4][4];
#pragma unroll
    for (int i = 0; i < 2; i++)
#pragma unroll
        for (int j = 0; j < 4; j++)
#pragma unroll
            for (int q = 0; q < 4; q++) acc[i][j][q] = 0.f;

    uint32_t aRow = sb + ((mb + (lid & 15)) * A1STR + (lid >> 4) * 8) * 2;
    uint32_t bRowH = sb + SM1_BH + ((nb + (lid & 15)) * A1STR + (lid >> 4) * 8) * 2;
    uint32_t bRowL = bRowH + (SM1_BL - SM1_BH);
#pragma unroll
    for (int ks = 0; ks < 8; ks++) {
        uint32_t ko = ks * 32;
        uint32_t a0[4], a1[4], b0[4], b1[4];
        ldm4(a0, aRow + ko);
        ldm4(a1, aRow + 16 * A1STR * 2 + ko);
        ldm4(b0, bRowH + ko);
        ldm4(b1, bRowH + 16 * A1STR * 2 + ko);
#pragma unroll
        for (int mt = 0; mt < 2; mt++) {
            const uint32_t* a = mt ? a1 : a0;
            mmaf16(acc[mt][0], a, b0[0], b0[2]);
            mmaf16(acc[mt][1], a, b0[1], b0[3]);
            mmaf16(acc[mt][2], a, b1[0], b1[2]);
            mmaf16(acc[mt][3], a, b1[1], b1[3]);
        }
        ldm4(b0, bRowL + ko);
        ldm4(b1, bRowL + 16 * A1STR * 2 + ko);
#pragma unroll
        for (int mt = 0; mt < 2; mt++) {
            const uint32_t* a = mt ? a1 : a0;
            mmaf16(acc[mt][0], a, b0[0], b0[2]);
            mmaf16(acc[mt][1], a, b0[1], b0[3]);
            mmaf16(acc[mt][2], a, b1[0], b1[2]);
            mmaf16(acc[mt][3], a, b1[1], b1[3]);
        }
    }
    __syncthreads();   // A region free -> staging

    __half* st = (__half*)sm;   // stride 72 halves
#pragma unroll
    for (int mt = 0; mt < 2; mt++) {
        int g = mb + mt * 16 + (lid >> 2);
#pragma unroll
        for (int nt = 0; nt < 4; nt++) {
            int col = nb + nt * 8 + (lid & 3) * 2;
            *(__half2*)(st + g * 72 + col)       = __float22half2_rn(make_float2(acc[mt][nt][0], acc[mt][nt][1]));
            *(__half2*)(st + (g + 8) * 72 + col) = __float22half2_rn(make_float2(acc[mt][nt][2], acc[mt][nt][3]));
        }
    }
#pragma unroll
    for (int nt = 0; nt < 4; nt++)
#pragma unroll
        for (int j = 0; j < 2; j++) {
            float v = 0.f, q = 0.f;
#pragma unroll
            for (int mt = 0; mt < 2; mt++) {
                float a = acc[mt][nt][j], b = acc[mt][nt][j + 2];
                v += a + b;
                q = fmaf(a, a, q); q = fmaf(b, b, q);
            }
            red4(v); red4(q);
            if (lid < 4) {
                int col = nb + nt * 8 + lid * 2 + j;
                atomicAdd(&s_sum[col], v);
                atomicAdd(&s_sum[64 + col], q);
            }
        }
    __syncthreads();
    {   // write y1 (permuted rows), 64B per thread
        int r = tid >> 1, h = tid & 1;
        size_t mm = m0 + r;
        int bb = (int)(mm / 196);
        int rem = (int)(mm - (size_t)bb * 196);
        int OH = rem / 14, OW = rem - OH * 14;
        __half* dst = g_y1h + (((size_t)bb * 7 + (OH >> 1)) * 7 + (OW >> 1)) * 256 +
                      ((((OH & 1) << 1) | (OW & 1)) << 6) + h * 32;
        const __half* srow = st + r * 72 + h * 32;
#pragma unroll
        for (int q = 0; q < 4; q++) ((uint4*)dst)[q] = ((const uint4*)srow)[q];
    }
    if (tid < 64) {
        atomicAdd(&g_stats[64 + tid], (double)s_sum[tid]);
        atomicAdd(&g_stats[128 + tid], (double)s_sum[64 + tid]);
    }
}

// ======================= conv2: HMMA GEMM  M=401408(x128), N=128, K=256 =======================
// A chunk [128][136] @0 | Bhi [128][264] @34816 | Blo @102400 | ssc@169984 ssh@170240 | s_sum@170496 (256 f)
#define A2STR 136
#define B2STR 264
#define SM2_BH 34816
#define SM2_BL 102400
#define SM2_BYTES 171520

__global__ void __launch_bounds__(256) conv2_k() {
    extern __shared__ __align__(16) char sm[];
    uint32_t sb = s2u(sm);
    float* ssc   = (float*)(sm + 169984);
    float* ssh   = (float*)(sm + 170240);
    float* s_sum = (float*)(sm + 170496);   // 128 sum | 128 sq
    int tid = threadIdx.x, wid = tid >> 5, lid = tid & 31;
    if (tid < 64) { ssc[tid] = g_s1[tid]; ssh[tid] = g_t1[tid]; }
    if (tid < 256) s_sum[tid] = 0.f;
    {
        const uint4* s1 = (const uint4*)g_B2hi;
        const uint4* s2 = (const uint4*)g_B2lo;
        for (int i = tid; i < 4096; i += 256) {
            int r = i >> 5, c = i & 31;
            *(uint4*)(sm + SM2_BH + (r * B2STR + c * 8) * 2) = s1[i];
            *(uint4*)(sm + SM2_BL + (r * B2STR + c * 8) * 2) = s2[i];
        }
    }
    size_t m0 = (size_t)blockIdx.x * 128;
    int wr = wid & 3, wc = wid >> 2;           // 4(m) x 2(n), warp tile 32 x 64
    int mb = wr * 32, nb = wc * 64;
    float acc[2][8][4];
#pragma unroll
    for (int i = 0; i < 2; i++)
#pragma unroll
        for (int j = 0; j < 8; j++)
#pragma unroll
            for (int q = 0; q < 4; q++) acc[i][j][q] = 0.f;

    uint32_t aRow = sb + ((mb + (lid & 15)) * A2STR + (lid >> 4) * 8) * 2;
    uint32_t bRow = sb + SM2_BH + ((nb + (lid & 15)) * B2STR + (lid >> 4) * 8) * 2;

    for (int kc = 0; kc < 2; kc++) {
        __syncthreads();
        {   // A chunk, BN1+ReLU folded
            int r = tid >> 1, h = tid & 1;
            const uint4* src = (const uint4*)(g_y1h + (m0 + r) * 256 + kc * 128 + h * 64);
#pragma unroll
            for (int i = 0; i < 8; i++) {
                uint4 v = src[i];
                int k0 = h * 64 + i * 8;
                __half2* hp = (__half2*)&v;
#pragma unroll
                for (int j = 0; j < 4; j++) {
                    int c = (kc * 128 + k0 + 2 * j) & 63;
                    float2 f = __half22float2(hp[j]);
                    f.x = fmaxf(fmaf(f.x, ssc[c], ssh[c]), 0.f);
                    f.y = fmaxf(fmaf(f.y, ssc[c + 1], ssh[c + 1]), 0.f);
                    hp[j] = __float22half2_rn(f);
                }
                *(uint4*)(sm + (r * A2STR + k0) * 2) = v;
            }
        }
        __syncthreads();
#pragma unroll
        for (int ks = 0; ks < 8; ks++) {
            uint32_t ko = kc * 256 + ks * 32;       // byte offset into B rows
            uint32_t ka = ks * 32;                  // byte offset into A chunk
            uint32_t a0[4], a1[4], b0[4], b1[4];
            ldm4(a0, aRow + ka);
            ldm4(a1, aRow + 16 * A2STR * 2 + ka);
#pragma unroll
            for (int half = 0; half < 2; half++) {  // n 0-31, 32-63 of warp tile
                uint32_t bh = bRow + half * 32 * B2STR * 2;
                ldm4(b0, bh + ko);
                ldm4(b1, bh + 16 * B2STR * 2 + ko);
#pragma unroll
                for (int mt = 0; mt < 2; mt++) {
                    const uint32_t* a = mt ? a1 : a0;
                    mmaf16(acc[mt][half * 4 + 0], a, b0[0], b0[2]);
                    mmaf16(acc[mt][half * 4 + 1], a, b0[1], b0[3]);
                    mmaf16(acc[mt][half * 4 + 2], a, b1[0], b1[2]);
                    mmaf16(acc[mt][half * 4 + 3], a, b1[1], b1[3]);
                }
                bh += (SM2_BL - SM2_BH);            // lo pass
                ldm4(b0, bh + ko);
                ldm4(b1, bh + 16 * B2STR * 2 + ko);
#pragma unroll
                for (int mt = 0; mt < 2; mt++) {
                    const uint32_t* a = mt ? a1 : a0;
                    mmaf16(acc[mt][half * 4 + 0], a, b0[0], b0[2]);
                    mmaf16(acc[mt][half * 4 + 1], a, b0[1], b0[3]);
                    mmaf16(acc[mt][half * 4 + 2], a, b1[0], b1[2]);
                    mmaf16(acc[mt][half * 4 + 3], a, b1[1], b1[3]);
                }
            }
        }
    }
    __syncthreads();   // A region free -> staging

    __half* st = (__half*)sm;   // stride 136 halves
#pragma unroll
    for (int mt = 0; mt < 2; mt++) {
        int g = mb + mt * 16 + (lid >> 2);
#pragma unroll
        for (int nt = 0; nt < 8; nt++) {
            int col = nb + (nt & 3) * 8 + (nt >> 2) * 32 + (lid & 3) * 2;
            *(__half2*)(st + g * 136 + col)       = __float22half2_rn(make_float2(acc[mt][nt][0], acc[mt][nt][1]));
            *(__half2*)(st + (g + 8) * 136 + col) = __float22half2_rn(make_float2(acc[mt][nt][2], acc[mt][nt][3]));
        }
    }
#pragma unroll
    for (int nt = 0; nt < 8; nt++)
#pragma unroll
        for (int j = 0; j < 2; j++) {
            float v = 0.f, q = 0.f;
#pragma unroll
            for (int mt = 0; mt < 2; mt++) {
                float a = acc[mt][nt][j], b = acc[mt][nt][j + 2];
                v += a + b;
                q = fmaf(a, a, q); q = fmaf(b, b, q);
            }
            red4(v); red4(q);
            if (lid < 4) {
                int col = nb + (nt & 3) * 8 + (nt >> 2) * 32 + lid * 2 + j;
                atomicAdd(&s_sum[col], v);
                atomicAdd(&s_sum[128 + col], q);
            }
        }
    __syncthreads();
    {   // write y2 row-major [m][128]
        int r = tid >> 1, h = tid & 1;
        __half* dst = g_y2h + (m0 + r) * 128 + h * 64;
        const __half* srow = st + r * 136 + h * 64;
#pragma unroll
        for (int q = 0; q < 8; q++) ((uint4*)dst)[q] = ((const uint4*)srow)[q];
    }
    if (tid < 128) {
        atomicAdd(&g_stats[192 + tid], (double)s_sum[tid]);
        atomicAdd(&g_stats[320 + tid], (double)s_sum[128 + tid]);
    }
}

// ---------------- final: BN2+ReLU, avg-pool 49, FC 128->10 ----------------
__global__ void __launch_bounds__(128) final_k(const float* __restrict__ wfc,
                                               const float* __restrict__ bfc,
                                               float* __restrict__ out) {
    __shared__ float f[128];
    int b = blockIdx.x, tid = threadIdx.x;
    const __half* y = g_y2h + (size_t)b * 49 * 128;
    float s = g_s2[tid], t = g_t2[tid];
    float acc = 0.f;
#pragma unroll 7
    for (int p = 0; p < 49; p++) acc += fmaxf(fmaf(__half2float(y[p * 128 + tid]), s, t), 0.f);
    f[tid] = acc * (1.f / 49.f);
    __syncthreads();
    if (tid < 10) {
        float o = bfc[tid];
        const float* wr = wfc + tid * 128;
#pragma unroll 8
        for (int c2 = 0; c2 < 128; c2++) o = fmaf(f[c2], wr[c2], o);
        out[(size_t)b * 10 + tid] = o;
    }
}

// ---------------- launch ----------------
extern "C" void kernel_launch(void* const* d_in, const int* in_sizes, int n_in,
                              void* d_out, int out_size) {
    const float* x   = (const float*)d_in[0];
    const float* w0  = (const float*)d_in[1];
    const float* g0  = (const float*)d_in[3];
    const float* be0 = (const float*)d_in[4];
    const float* w1  = (const float*)d_in[5];
    const float* g1  = (const float*)d_in[7];
    const float* be1 = (const float*)d_in[8];
    const float* w2  = (const float*)d_in[9];
    const float* g2  = (const float*)d_in[11];
    const float* be2 = (const float*)d_in[12];
    const float* wfc = (const float*)d_in[13];
    const float* bfc = (const float*)d_in[14];
    float* out = (float*)d_out;

    cudaFuncSetAttribute(conv1_k, cudaFuncAttributeMaxDynamicSharedMemorySize, SM1_BYTES);
    cudaFuncSetAttribute(conv2_k, cudaFuncAttributeMaxDynamicSharedMemorySize, SM2_BYTES);

    prep_k<<<128, 256>>>(w1, w2);
    conv0_k<<<BATCH, 256>>>(x, w0);
    scale0_k<<<1, 32>>>(g0, be0);
    conv1_k<<<12544, 256, SM1_BYTES>>>();
    scale1_k<<<1, 64>>>(g1, be1);
    conv2_k<<<3136, 256, SM2_BYTES>>>();
    scale2_k<<<1, 128>>>(g2, be2);
    final_k<<<BATCH, 128>>>(wfc, bfc, out);
}

// round 8
// speedup vs baseline: 2.2945x; 1.0166x over previous
#include <cuda_runtime.h>
#include <cuda_fp16.h>
#include <cstdint>

#define BATCH 8192

// ---------------- scratch ----------------
__device__ __align__(16) __half g_y0h[(size_t)BATCH * 196 * 128];   // [b][14][14][khw(4)][c(32)] raw conv0
__device__ __align__(16) __half g_y1h[(size_t)BATCH * 49 * 256];    // [b][7][7][khw(4)][c(64)]   raw conv1
__device__ __align__(16) __half g_y2h[(size_t)BATCH * 49 * 128];    // [b][49][c(128)]            raw conv2
__device__ double g_stats[448];
__device__ float  g_s0[32], g_t0[32], g_s1[64], g_t1[64], g_s2[128], g_t2[128];
// B operands pre-arranged in mma fragment-lane order:
// B1f: [nw(2)][ks(8)][lane(32)][hi:16 halves | lo:16 halves]   (32KB)
// B2f: [nh(2)][nw(2)][ks(16)][lane(32)][hi 16 | lo 16]         (128KB)
__device__ __align__(16) __half g_B1f[16384];
__device__ __align__(16) __half g_B2f[65536];

// ---------------- helpers ----------------
__device__ __forceinline__ uint32_t s2u(const void* p) {
    uint32_t a;
    asm("{ .reg .u64 t; cvta.to.shared.u64 t, %1; cvt.u32.u64 %0, t; }" : "=r"(a) : "l"(p));
    return a;
}
__device__ __forceinline__ void ldm4(uint32_t* r, uint32_t addr) {
    asm volatile("ldmatrix.sync.aligned.m8n8.x4.shared.b16 {%0,%1,%2,%3}, [%4];"
                 : "=r"(r[0]), "=r"(r[1]), "=r"(r[2]), "=r"(r[3]) : "r"(addr));
}
__device__ __forceinline__ void mmaf16(float* d, const uint32_t* a, uint32_t b0, uint32_t b1) {
    asm volatile("mma.sync.aligned.m16n8k16.row.col.f32.f16.f16.f32 "
                 "{%0,%1,%2,%3}, {%4,%5,%6,%7}, {%8,%9}, {%0,%1,%2,%3};"
                 : "+f"(d[0]), "+f"(d[1]), "+f"(d[2]), "+f"(d[3])
                 : "r"(a[0]), "r"(a[1]), "r"(a[2]), "r"(a[3]), "r"(b0), "r"(b1));
}
__device__ __forceinline__ void red4(float& v) {   // sum lanes sharing (lane&3)
    v += __shfl_xor_sync(0xFFFFFFFFu, v, 4);
    v += __shfl_xor_sync(0xFFFFFFFFu, v, 8);
    v += __shfl_xor_sync(0xFFFFFFFFu, v, 16);
}
__device__ __forceinline__ void cpasync16(uint32_t dst, const void* src) {
    asm volatile("cp.async.cg.shared.global [%0], [%1], 16;" :: "r"(dst), "l"(src));
}
#define CP_COMMIT asm volatile("cp.async.commit_group;" ::: "memory")
#define CP_WAIT1  asm volatile("cp.async.wait_group 1;" ::: "memory")
#define CP_WAIT0  asm volatile("cp.async.wait_group 0;" ::: "memory")

__device__ __forceinline__ void norm2(uint32_t& r, float s0, float t0, float s1, float t1) {
    __half2 h = *(__half2*)&r;
    float2 f = __half22float2(h);
    f.x = fmaxf(fmaf(f.x, s0, t0), 0.f);
    f.y = fmaxf(fmaf(f.y, s1, t1), 0.f);
    h = __float22half2_rn(f);
    r = *(uint32_t*)&h;
}

// compute 4 k-steps of one chunk: A frags from smem (raw), normalize in regs, B frags via LDG
__device__ __forceinline__ void gchunk(uint32_t aB, const uint4* __restrict__ Bf, int ks0, int cmask,
                                       float srA, float trA, float srB, float trB,
                                       int lid, float acc[2][4][4]) {
#pragma unroll
    for (int ksl = 0; ksl < 4; ksl++) {
        int ks = ks0 + ksl;
        uint32_t a0[4], a1[4];
        ldm4(a0, aB + ksl * 32);
        ldm4(a1, aB + 16 * 72 * 2 + ksl * 32);
        int cbase = (ks * 16) & cmask;
        float sr = (cbase & 32) ? srB : srA;
        float tr = (cbase & 32) ? trB : trA;
        int cb = (cbase & 31) + (lid & 3) * 2;
        float sA = __shfl_sync(0xFFFFFFFFu, sr, cb),     tA = __shfl_sync(0xFFFFFFFFu, tr, cb);
        float sB = __shfl_sync(0xFFFFFFFFu, sr, cb + 1), tB = __shfl_sync(0xFFFFFFFFu, tr, cb + 1);
        float sC = __shfl_sync(0xFFFFFFFFu, sr, cb + 8), tC = __shfl_sync(0xFFFFFFFFu, tr, cb + 8);
        float sD = __shfl_sync(0xFFFFFFFFu, sr, cb + 9), tD = __shfl_sync(0xFFFFFFFFu, tr, cb + 9);
        norm2(a0[0], sA, tA, sB, tB); norm2(a0[1], sA, tA, sB, tB);
        norm2(a0[2], sC, tC, sD, tD); norm2(a0[3], sC, tC, sD, tD);
        norm2(a1[0], sA, tA, sB, tB); norm2(a1[1], sA, tA, sB, tB);
        norm2(a1[2], sC, tC, sD, tD); norm2(a1[3], sC, tC, sD, tD);
        const uint4* bp = Bf + (size_t)(ks * 32 + lid) * 4;
        uint4 b0 = bp[0], b1 = bp[1];                 // hi pass
#pragma unroll
        for (int mt = 0; mt < 2; mt++) {
            const uint32_t* a = mt ? a1 : a0;
            mmaf16(acc[mt][0], a, b0.x, b0.y);
            mmaf16(acc[mt][1], a, b0.z, b0.w);
            mmaf16(acc[mt][2], a, b1.x, b1.y);
            mmaf16(acc[mt][3], a, b1.z, b1.w);
        }
        uint4 b2 = bp[2], b3 = bp[3];                 // lo pass
#pragma unroll
        for (int mt = 0; mt < 2; mt++) {
            const uint32_t* a = mt ? a1 : a0;
            mmaf16(acc[mt][0], a, b2.x, b2.y);
            mmaf16(acc[mt][1], a, b2.z, b2.w);
            mmaf16(acc[mt][2], a, b3.x, b3.y);
            mmaf16(acc[mt][3], a, b3.z, b3.w);
        }
    }
}

// ---------------- prep: zero stats, build fragment-order hi/lo B images ----------------
__global__ void prep_k(const float* __restrict__ w1, const float* __restrict__ w2) {
    int t0 = blockIdx.x * blockDim.x + threadIdx.x, stride = blockDim.x * gridDim.x;
    for (int i = t0; i < 448; i += stride) g_stats[i] = 0.0;
    for (int i = t0; i < 16384; i += stride) {
        int pos = i & 31, lane = (i >> 5) & 31, ks = (i >> 10) & 7, nw = i >> 13;
        int pass = pos >> 4, w16 = pos & 15, t = w16 >> 2, reg = (w16 >> 1) & 1, h = w16 & 1;
        int n = nw * 32 + t * 8 + (lane >> 2);
        int k = ks * 16 + (lane & 3) * 2 + reg * 8 + h;
        int khw = k >> 5, c = k & 31;
        float w = w1[((n * 32 + c) * 2 + (khw >> 1)) * 2 + (khw & 1)];
        __half hi = __float2half_rn(w);
        g_B1f[i] = pass ? __float2half_rn(w - __half2float(hi)) : hi;
    }
    for (int i = t0; i < 65536; i += stride) {
        int pos = i & 31, lane = (i >> 5) & 31, ks = (i >> 10) & 15, nw = (i >> 14) & 1, nh = i >> 15;
        int pass = pos >> 4, w16 = pos & 15, t = w16 >> 2, reg = (w16 >> 1) & 1, h = w16 & 1;
        int n = nh * 64 + nw * 32 + t * 8 + (lane >> 2);
        int k = ks * 16 + (lane & 3) * 2 + reg * 8 + h;
        int khw = k >> 6, c = k & 63;
        float w = w2[((n * 64 + c) * 2 + (khw >> 1)) * 2 + (khw & 1)];
        __half hi = __float2half_rn(w);
        g_B2f[i] = pass ? __float2half_rn(w - __half2float(hi)) : hi;
    }
}

// ---------------- conv0: 1->32, 3x3 SAME, raw fp16 output + exact fp32 stats ----------------
__global__ void __launch_bounds__(256) conv0_k(const float* __restrict__ x, const float* __restrict__ w0) {
    __shared__ float sx[900];
    __shared__ float rs[256], rq[256];
    int b = blockIdx.x, tid = threadIdx.x;
    for (int i = tid; i < 900; i += 256) sx[i] = 0.f;
    __syncthreads();
    const float* xb = x + (size_t)b * 784;
    for (int i = tid; i < 784; i += 256) {
        int r = i / 28, c = i - r * 28;
        sx[(r + 1) * 30 + c + 1] = xb[i];
    }
    __syncthreads();
    int c = tid & 31, p = tid >> 5;
    float w[9];
#pragma unroll
    for (int i = 0; i < 9; i++) w[i] = w0[c * 9 + i];
    float sum = 0.f, sq = 0.f;
    __half* outb = g_y0h + (size_t)b * (196 * 128);
    for (int it = 0; it < 98; it++) {
        int pix = it * 8 + p;
        int OH = pix / 28, OW = pix - OH * 28;
        const float* s = &sx[OH * 30 + OW];
        float acc = w[0] * s[0];
        acc = fmaf(w[1], s[1], acc);  acc = fmaf(w[2], s[2], acc);
        acc = fmaf(w[3], s[30], acc); acc = fmaf(w[4], s[31], acc); acc = fmaf(w[5], s[32], acc);
        acc = fmaf(w[6], s[60], acc); acc = fmaf(w[7], s[61], acc); acc = fmaf(w[8], s[62], acc);
        int oh = OH >> 1, ow = OW >> 1, khw = ((OH & 1) << 1) | (OW & 1);
        outb[(size_t)((oh * 14 + ow) * 4 + khw) * 32 + c] = __float2half_rn(acc);
        sum += acc;
        sq = fmaf(acc, acc, sq);
    }
    rs[tid] = sum; rq[tid] = sq;
    __syncthreads();
    if (p == 0) {
        float S = 0.f, Q = 0.f;
#pragma unroll
        for (int j = 0; j < 8; j++) { S += rs[j * 32 + c]; Q += rq[j * 32 + c]; }
        atomicAdd(&g_stats[c], (double)S);
        atomicAdd(&g_stats[32 + c], (double)Q);
    }
}

// ---------------- scale kernels ----------------
__global__ void scale0_k(const float* __restrict__ g, const float* __restrict__ be) {
    int c = threadIdx.x;
    const double invN = 1.0 / 6422528.0;
    double mean = g_stats[c] * invN;
    double var  = g_stats[32 + c] * invN - mean * mean;
    double s = (double)g[c] / sqrt(var + 1e-5);
    g_s0[c] = (float)s; g_t0[c] = (float)((double)be[c] - mean * s);
}
__global__ void scale1_k(const float* __restrict__ g, const float* __restrict__ be) {
    int c = threadIdx.x;
    const double invN = 1.0 / 1605632.0;
    double mean = g_stats[64 + c] * invN;
    double var  = g_stats[128 + c] * invN - mean * mean;
    double s = (double)g[c] / sqrt(var + 1e-5);
    g_s1[c] = (float)s; g_t1[c] = (float)((double)be[c] - mean * s);
}
__global__ void scale2_k(const float* __restrict__ g, const float* __restrict__ be) {
    int c = threadIdx.x;
    const double invN = 1.0 / 401408.0;
    double mean = g_stats[192 + c] * invN;
    double var  = g_stats[320 + c] * invN - mean * mean;
    double s = (double)g[c] / sqrt(var + 1e-5);
    g_s2[c] = (float)s; g_t2[c] = (float)((double)be[c] - mean * s);
}

// ======================= conv1: HMMA GEMM  M=1605632(x128), N=64, K=128 =======================
// smem: 2 async A chunks [128][72] halves + 128-float reduce buffer  (~37KB, 3 CTAs/SM)
__global__ void __launch_bounds__(256, 3) conv1_k() {
    __shared__ __align__(16) __half Ab[2][128 * 72];
    __shared__ float s_red[128];
    int tid = threadIdx.x, wid = tid >> 5, lid = tid & 31;
    size_t m0 = (size_t)blockIdx.x * 128;
    const __half* Asrc = g_y0h + m0 * 128;
#pragma unroll
    for (int kc = 0; kc < 2; kc++) {
#pragma unroll
        for (int i = 0; i < 4; i++) {
            int idx = tid + i * 256;
            int row = idx >> 3, c8 = idx & 7;
            cpasync16(s2u(&Ab[kc][row * 72 + c8 * 8]), Asrc + row * 128 + kc * 64 + c8 * 8);
        }
        CP_COMMIT;
    }
    if (tid < 128) s_red[tid] = 0.f;
    float sreg = g_s0[lid], treg = g_t0[lid];
    int mb = (wid & 3) * 32, wc = wid >> 2, nb = wc * 32;
    float acc[2][4][4];
#pragma unroll
    for (int i = 0; i < 2; i++)
#pragma unroll
        for (int j = 0; j < 4; j++)
#pragma unroll
            for (int q = 0; q < 4; q++) acc[i][j][q] = 0.f;
    const uint4* Bf = ((const uint4*)g_B1f) + (size_t)wc * 1024;
    uint32_t aB0 = s2u(&Ab[0][(mb + (lid & 15)) * 72 + (lid >> 4) * 8]);
    uint32_t aB1 = s2u(&Ab[1][(mb + (lid & 15)) * 72 + (lid >> 4) * 8]);

    CP_WAIT1; __syncthreads();
    gchunk(aB0, Bf, 0, 31, sreg, treg, sreg, treg, lid, acc);
    CP_WAIT0; __syncthreads();
    gchunk(aB1, Bf, 4, 31, sreg, treg, sreg, treg, lid, acc);
    __syncthreads();

    // epilogue: stage fp16 result (stride 72), stats, permuted y1 write
    __half* st = (__half*)Ab;
#pragma unroll
    for (int mt = 0; mt < 2; mt++) {
        int g = mb + mt * 16 + (lid >> 2);
#pragma unroll
        for (int nt = 0; nt < 4; nt++) {
            int col = nb + nt * 8 + (lid & 3) * 2;
            *(__half2*)(st + g * 72 + col)       = __float22half2_rn(make_float2(acc[mt][nt][0], acc[mt][nt][1]));
            *(__half2*)(st + (g + 8) * 72 + col) = __float22half2_rn(make_float2(acc[mt][nt][2], acc[mt][nt][3]));
        }
    }
#pragma unroll
    for (int nt = 0; nt < 4; nt++)
#pragma unroll
        for (int j = 0; j < 2; j++) {
            float v = 0.f, q = 0.f;
#pragma unroll
            for (int mt = 0; mt < 2; mt++) {
                float a = acc[mt][nt][j], b = acc[mt][nt][j + 2];
                v += a + b;
                q = fmaf(a, a, q); q = fmaf(b, b, q);
            }
            red4(v); red4(q);
            if (lid < 4) {
                int col = nb + nt * 8 + lid * 2 + j;
                atomicAdd(&s_red[col], v);
                atomicAdd(&s_red[64 + col], q);
            }
        }
    __syncthreads();
    {   // y1 write (permuted rows)
        int r = tid >> 1, h = tid & 1;
        size_t mm = m0 + r;
        int bb = (int)(mm / 196);
        int rem = (int)(mm - (size_t)bb * 196);
        int OH = rem / 14, OW = rem - OH * 14;
        __half* dst = g_y1h + (((size_t)bb * 7 + (OH >> 1)) * 7 + (OW >> 1)) * 256 +
                      ((((OH & 1) << 1) | (OW & 1)) << 6) + h * 32;
        const __half* srow = st + r * 72 + h * 32;
#pragma unroll
        for (int q = 0; q < 4; q++) ((uint4*)dst)[q] = ((const uint4*)srow)[q];
    }
    if (tid < 64) {
        atomicAdd(&g_stats[64 + tid], (double)s_red[tid]);
        atomicAdd(&g_stats[128 + tid], (double)s_red[64 + tid]);
    }
}

// ======================= conv2: HMMA GEMM  M=401408(x128), N=128(2x64), K=256 =======================
__global__ void __launch_bounds__(256, 3) conv2_k() {
    __shared__ __align__(16) __half Ab[2][128 * 72];
    __shared__ float s_red[128];
    int tid = threadIdx.x, wid = tid >> 5, lid = tid & 31;
    size_t m0 = (size_t)blockIdx.x * 128;
    int nh = blockIdx.y;
    const __half* Asrc = g_y1h + m0 * 256;
#pragma unroll
    for (int kc = 0; kc < 2; kc++) {
#pragma unroll
        for (int i = 0; i < 4; i++) {
            int idx = tid + i * 256;
            int row = idx >> 3, c8 = idx & 7;
            cpasync16(s2u(&Ab[kc][row * 72 + c8 * 8]), Asrc + row * 256 + kc * 64 + c8 * 8);
        }
        CP_COMMIT;
    }
    if (tid < 128) s_red[tid] = 0.f;
    float srA = g_s1[lid], trA = g_t1[lid];
    float srB = g_s1[32 + lid], trB = g_t1[32 + lid];
    int mb = (wid & 3) * 32, wc = wid >> 2, nb = wc * 32;
    float acc[2][4][4];
#pragma unroll
    for (int i = 0; i < 2; i++)
#pragma unroll
        for (int j = 0; j < 4; j++)
#pragma unroll
            for (int q = 0; q < 4; q++) acc[i][j][q] = 0.f;
    const uint4* Bf = ((const uint4*)g_B2f) + (size_t)(nh * 2 + wc) * 2048;
    uint32_t aB0 = s2u(&Ab[0][(mb + (lid & 15)) * 72 + (lid >> 4) * 8]);
    uint32_t aB1 = s2u(&Ab[1][(mb + (lid & 15)) * 72 + (lid >> 4) * 8]);

    CP_WAIT1; __syncthreads();
    gchunk(aB0, Bf, 0, 63, srA, trA, srB, trB, lid, acc);
    __syncthreads();
#pragma unroll
    for (int i = 0; i < 4; i++) {
        int idx = tid + i * 256;
        int row = idx >> 3, c8 = idx & 7;
        cpasync16(s2u(&Ab[0][row * 72 + c8 * 8]), Asrc + row * 256 + 2 * 64 + c8 * 8);
    }
    CP_COMMIT;
    CP_WAIT1; __syncthreads();
    gchunk(aB1, Bf, 4, 63, srA, trA, srB, trB, lid, acc);
    __syncthreads();
#pragma unroll
    for (int i = 0; i < 4; i++) {
        int idx = tid + i * 256;
        int row = idx >> 3, c8 = idx & 7;
        cpasync16(s2u(&Ab[1][row * 72 + c8 * 8]), Asrc + row * 256 + 3 * 64 + c8 * 8);
    }
    CP_COMMIT;
    CP_WAIT1; __syncthreads();
    gchunk(aB0, Bf, 8, 63, srA, trA, srB, trB, lid, acc);
    CP_WAIT0; __syncthreads();
    gchunk(aB1, Bf, 12, 63, srA, trA, srB, trB, lid, acc);
    __syncthreads();

    // epilogue
    __half* st = (__half*)Ab;
#pragma unroll
    for (int mt = 0; mt < 2; mt++) {
        int g = mb + mt * 16 + (lid >> 2);
#pragma unroll
        for (int nt = 0; nt < 4; nt++) {
            int col = nb + nt * 8 + (lid & 3) * 2;
            *(__half2*)(st + g * 72 + col)       = __float22half2_rn(make_float2(acc[mt][nt][0], acc[mt][nt][1]));
            *(__half2*)(st + (g + 8) * 72 + col) = __float22half2_rn(make_float2(acc[mt][nt][2], acc[mt][nt][3]));
        }
    }
#pragma unroll
    for (int nt = 0; nt < 4; nt++)
#pragma unroll
        for (int j = 0; j < 2; j++) {
            float v = 0.f, q = 0.f;
#pragma unroll
            for (int mt = 0; mt < 2; mt++) {
                float a = acc[mt][nt][j], b = acc[mt][nt][j + 2];
                v += a + b;
                q = fmaf(a, a, q); q = fmaf(b, b, q);
            }
            red4(v); red4(q);
            if (lid < 4) {
                int col = nb + nt * 8 + lid * 2 + j;
                atomicAdd(&s_red[col], v);
                atomicAdd(&s_red[64 + col], q);
            }
        }
    __syncthreads();
    {   // y2 write row-major, this CTA's 64-col half
        int r = tid >> 1, h = tid & 1;
        __half* dst = g_y2h + (m0 + r) * 128 + nh * 64 + h * 32;
        const __half* srow = st + r * 72 + h * 32;
#pragma unroll
        for (int q = 0; q < 4; q++) ((uint4*)dst)[q] = ((const uint4*)srow)[q];
    }
    if (tid < 64) {
        atomicAdd(&g_stats[192 + nh * 64 + tid], (double)s_red[tid]);
        atomicAdd(&g_stats[320 + nh * 64 + tid], (double)s_red[64 + tid]);
    }
}

// ---------------- final: BN2+ReLU, avg-pool 49, FC 128->10 ----------------
__global__ void __launch_bounds__(128) final_k(const float* __restrict__ wfc,
                                               const float* __restrict__ bfc,
                                               float* __restrict__ out) {
    __shared__ float f[128];
    int b = blockIdx.x, tid = threadIdx.x;
    const __half* y = g_y2h + (size_t)b * 49 * 128;
    float s = g_s2[tid], t = g_t2[tid];
    float acc = 0.f;
#pragma unroll 7
    for (int p = 0; p < 49; p++) acc += fmaxf(fmaf(__half2float(y[p * 128 + tid]), s, t), 0.f);
    f[tid] = acc * (1.f / 49.f);
    __syncthreads();
    if (tid < 10) {
        float o = bfc[tid];
        const float* wr = wfc + tid * 128;
#pragma unroll 8
        for (int c2 = 0; c2 < 128; c2++) o = fmaf(f[c2], wr[c2], o);
        out[(size_t)b * 10 + tid] = o;
    }
}

// ---------------- launch ----------------
extern "C" void kernel_launch(void* const* d_in, const int* in_sizes, int n_in,
                              void* d_out, int out_size) {
    const float* x   = (const float*)d_in[0];
    const float* w0  = (const float*)d_in[1];
    const float* g0  = (const float*)d_in[3];
    const float* be0 = (const float*)d_in[4];
    const float* w1  = (const float*)d_in[5];
    const float* g1  = (const float*)d_in[7];
    const float* be1 = (const float*)d_in[8];
    const float* w2  = (const float*)d_in[9];
    const float* g2  = (const float*)d_in[11];
    const float* be2 = (const float*)d_in[12];
    const float* wfc = (const float*)d_in[13];
    const float* bfc = (const float*)d_in[14];
    float* out = (float*)d_out;

    prep_k<<<128, 256>>>(w1, w2);
    conv0_k<<<BATCH, 256>>>(x, w0);
    scale0_k<<<1, 32>>>(g0, be0);
    conv1_k<<<12544, 256>>>();
    scale1_k<<<1, 64>>>(g1, be1);
    conv2_k<<<dim3(3136, 2), 256>>>();
    scale2_k<<<1, 128>>>(g2, be2);
    final_k<<<BATCH, 128>>>(wfc, bfc, out);
}

// round 11
// speedup vs baseline: 3.3157x; 1.4451x over previous
#include <cuda_runtime.h>
#include <cuda_fp16.h>
#include <cstdint>

#define BATCH 8192

// ---------------- scratch ----------------
__device__ __align__(16) __half g_y0h[(size_t)BATCH * 196 * 128];   // [b][14][14][khw(4)][c(32)] raw conv0
__device__ __align__(16) __half g_y1h[(size_t)BATCH * 49 * 256];    // [b][7][7][khw(4)][c(64)]   raw conv1
__device__ __align__(16) __half g_y2h[(size_t)BATCH * 49 * 128];    // [b][49][c(128)]            raw conv2
__device__ double g_stats[448];
__device__ float  g_s0[32], g_t0[32], g_s1[64], g_t1[64], g_s2[128], g_t2[128];
// B operands, fragment order, DENSE per-LDG:
// B1f: [nw(2)][ks(8)][q(4)][lane(32)][8 halves]   q = pass*2 + half16sel   (32KB)
// B2f: [nh(2)][nw(2)][ks(16)][q(4)][lane(32)][8 halves]                    (128KB)
__device__ __align__(16) __half g_B1f[16384];
__device__ __align__(16) __half g_B2f[65536];

// ---------------- helpers ----------------
#define H2(r) (*reinterpret_cast<__half2*>(&(r)))
__device__ __forceinline__ uint32_t s2u(const void* p) {
    uint32_t a;
    asm("{ .reg .u64 t; cvta.to.shared.u64 t, %1; cvt.u32.u64 %0, t; }" : "=r"(a) : "l"(p));
    return a;
}
__device__ __forceinline__ void ldm4(uint32_t* r, uint32_t addr) {
    asm volatile("ldmatrix.sync.aligned.m8n8.x4.shared.b16 {%0,%1,%2,%3}, [%4];"
                 : "=r"(r[0]), "=r"(r[1]), "=r"(r[2]), "=r"(r[3]) : "r"(addr));
}
__device__ __forceinline__ void mmaf16(float* d, const uint32_t* a, uint32_t b0, uint32_t b1) {
    asm volatile("mma.sync.aligned.m16n8k16.row.col.f32.f16.f16.f32 "
                 "{%0,%1,%2,%3}, {%4,%5,%6,%7}, {%8,%9}, {%0,%1,%2,%3};"
                 : "+f"(d[0]), "+f"(d[1]), "+f"(d[2]), "+f"(d[3])
                 : "r"(a[0]), "r"(a[1]), "r"(a[2]), "r"(a[3]), "r"(b0), "r"(b1));
}
__device__ __forceinline__ void red4(float& v) {
    v += __shfl_xor_sync(0xFFFFFFFFu, v, 4);
    v += __shfl_xor_sync(0xFFFFFFFFu, v, 8);
    v += __shfl_xor_sync(0xFFFFFFFFu, v, 16);
}
__device__ __forceinline__ void cpasync16(uint32_t dst, const void* src) {
    asm volatile("cp.async.cg.shared.global [%0], [%1], 16;" :: "r"(dst), "l"(src));
}
#define CP_COMMIT asm volatile("cp.async.commit_group;" ::: "memory")
#define CP_WAIT0  asm volatile("cp.async.wait_group 0;" ::: "memory")

// ---------------- prep: zero stats, dense fragment-order hi/lo B images ----------------
__global__ void prep_k(const float* __restrict__ w1, const float* __restrict__ w2) {
    int t0 = blockIdx.x * blockDim.x + threadIdx.x, stride = blockDim.x * gridDim.x;
    for (int i = t0; i < 448; i += stride) g_stats[i] = 0.0;
    for (int i = t0; i < 16384; i += stride) {
        int h = i & 1, reg = (i >> 1) & 1, t = (i >> 2) & 1, lane = (i >> 3) & 31;
        int q = (i >> 8) & 3, ks = (i >> 10) & 7, nw = (i >> 13) & 1;
        int pass = q >> 1, h16 = q & 1;
        int n = nw * 32 + h16 * 16 + t * 8 + (lane >> 2);
        int k = ks * 16 + (lane & 3) * 2 + reg * 8 + h;
        int khw = k >> 5, c = k & 31;
        float w = w1[((n * 32 + c) * 2 + (khw >> 1)) * 2 + (khw & 1)];
        __half hi = __float2half_rn(w);
        g_B1f[i] = pass ? __float2half_rn(w - __half2float(hi)) : hi;
    }
    for (int i = t0; i < 65536; i += stride) {
        int h = i & 1, reg = (i >> 1) & 1, t = (i >> 2) & 1, lane = (i >> 3) & 31;
        int q = (i >> 8) & 3, ks = (i >> 10) & 15, nw = (i >> 14) & 1, nh = (i >> 15) & 1;
        int pass = q >> 1, h16 = q & 1;
        int n = nh * 64 + nw * 32 + h16 * 16 + t * 8 + (lane >> 2);
        int k = ks * 16 + (lane & 3) * 2 + reg * 8 + h;
        int khw = k >> 6, c = k & 63;
        float w = w2[((n * 64 + c) * 2 + (khw >> 1)) * 2 + (khw & 1)];
        __half hi = __float2half_rn(w);
        g_B2f[i] = pass ? __float2half_rn(w - __half2float(hi)) : hi;
    }
}

// ---------------- conv0: 1->32, 3x3 SAME, raw fp16 output + exact fp32 stats ----------------
__global__ void __launch_bounds__(256) conv0_k(const float* __restrict__ x, const float* __restrict__ w0) {
    __shared__ float sx[900];
    __shared__ float rs[256], rq[256];
    int b = blockIdx.x, tid = threadIdx.x;
    for (int i = tid; i < 900; i += 256) sx[i] = 0.f;
    __syncthreads();
    const float* xb = x + (size_t)b * 784;
    for (int i = tid; i < 784; i += 256) {
        int r = i / 28, c = i - r * 28;
        sx[(r + 1) * 30 + c + 1] = xb[i];
    }
    __syncthreads();
    int c = tid & 31, p = tid >> 5;
    float w[9];
#pragma unroll
    for (int i = 0; i < 9; i++) w[i] = w0[c * 9 + i];
    float sum = 0.f, sq = 0.f;
    __half* outb = g_y0h + (size_t)b * (196 * 128);
    for (int it = 0; it < 98; it++) {
        int pix = it * 8 + p;
        int OH = pix / 28, OW = pix - OH * 28;
        const float* s = &sx[OH * 30 + OW];
        float acc = w[0] * s[0];
        acc = fmaf(w[1], s[1], acc);  acc = fmaf(w[2], s[2], acc);
        acc = fmaf(w[3], s[30], acc); acc = fmaf(w[4], s[31], acc); acc = fmaf(w[5], s[32], acc);
        acc = fmaf(w[6], s[60], acc); acc = fmaf(w[7], s[61], acc); acc = fmaf(w[8], s[62], acc);
        int oh = OH >> 1, ow = OW >> 1, khw = ((OH & 1) << 1) | (OW & 1);
        outb[(size_t)((oh * 14 + ow) * 4 + khw) * 32 + c] = __float2half_rn(acc);
        sum += acc;
        sq = fmaf(acc, acc, sq);
    }
    rs[tid] = sum; rq[tid] = sq;
    __syncthreads();
    if (p == 0) {
        float S = 0.f, Q = 0.f;
#pragma unroll
        for (int j = 0; j < 8; j++) { S += rs[j * 32 + c]; Q += rq[j * 32 + c]; }
        atomicAdd(&g_stats[c], (double)S);
        atomicAdd(&g_stats[32 + c], (double)Q);
    }
}

// ---------------- scale kernels ----------------
__global__ void scale0_k(const float* __restrict__ g, const float* __restrict__ be) {
    int c = threadIdx.x;
    const double invN = 1.0 / 6422528.0;
    double mean = g_stats[c] * invN;
    double var  = g_stats[32 + c] * invN - mean * mean;
    double s = (double)g[c] / sqrt(var + 1e-5);
    g_s0[c] = (float)s; g_t0[c] = (float)((double)be[c] - mean * s);
}
__global__ void scale1_k(const float* __restrict__ g, const float* __restrict__ be) {
    int c = threadIdx.x;
    const double invN = 1.0 / 1605632.0;
    double mean = g_stats[64 + c] * invN;
    double var  = g_stats[128 + c] * invN - mean * mean;
    double s = (double)g[c] / sqrt(var + 1e-5);
    g_s1[c] = (float)s; g_t1[c] = (float)((double)be[c] - mean * s);
}
__global__ void scale2_k(const float* __restrict__ g, const float* __restrict__ be) {
    int c = threadIdx.x;
    const double invN = 1.0 / 401408.0;
    double mean = g_stats[192 + c] * invN;
    double var  = g_stats[320 + c] * invN - mean * mean;
    double s = (double)g[c] / sqrt(var + 1e-5);
    g_s2[c] = (float)s; g_t2[c] = (float)((double)be[c] - mean * s);
}

// ======================= conv1: HMMA GEMM  M=1605632(x128), N=64, K=128 =======================
// 128 threads, warps 2(m)x2(n), warp tile 64x32. A single-shot cp.async [128][136].
#define A1STR 136
#define A1STEP (16 * A1STR * 2)
__global__ void __launch_bounds__(128) conv1_k() {
    __shared__ __align__(16) __half Ab[128 * A1STR];
    __shared__ float s_red[128];
    int tid = threadIdx.x, wid = tid >> 5, lid = tid & 31;
    size_t m0 = (size_t)blockIdx.x * 128;
    const __half* Asrc = g_y0h + m0 * 128;
#pragma unroll
    for (int i = 0; i < 16; i++) {
        int idx = tid + i * 128;
        int row = idx >> 4, c16 = idx & 15;
        cpasync16(s2u(&Ab[row * A1STR + c16 * 8]), Asrc + row * 128 + c16 * 8);
    }
    CP_COMMIT;
    if (tid < 128) s_red[tid] = 0.f;
    // packed BN scales + hoisted shuffles (2 variants: ks even/odd)
    int ch0 = (lid & 15) * 2;
    uint32_t spk, tpk;
    { __half2 sp = __floats2half2_rn(g_s0[ch0], g_s0[ch0 + 1]);
      __half2 tp = __floats2half2_rn(g_t0[ch0], g_t0[ch0 + 1]);
      spk = *(uint32_t*)&sp; tpk = *(uint32_t*)&tp; }
    uint32_t sc0[2], tc0[2], sc8[2], tc8[2];
#pragma unroll
    for (int v = 0; v < 2; v++) {
        int i0 = v * 8 + (lid & 3);
        sc0[v] = __shfl_sync(0xFFFFFFFFu, spk, i0);     tc0[v] = __shfl_sync(0xFFFFFFFFu, tpk, i0);
        sc8[v] = __shfl_sync(0xFFFFFFFFu, spk, i0 + 4); tc8[v] = __shfl_sync(0xFFFFFFFFu, tpk, i0 + 4);
    }
    int mw = wid & 1, nw = wid >> 1;
    int mb = mw * 64, nb = nw * 32;
    float acc[4][4][4];
#pragma unroll
    for (int i = 0; i < 4; i++)
#pragma unroll
        for (int j = 0; j < 4; j++)
#pragma unroll
            for (int q = 0; q < 4; q++) acc[i][j][q] = 0.f;
    const uint4* Bf = (const uint4*)g_B1f;
    uint32_t aB = s2u(&Ab[(mb + (lid & 15)) * A1STR + (lid >> 4) * 8]);
    CP_WAIT0;
    __syncthreads();
#pragma unroll
    for (int ks = 0; ks < 8; ks++) {
        uint32_t a[4][4];
#pragma unroll
        for (int mt = 0; mt < 4; mt++) ldm4(a[mt], aB + mt * A1STEP + ks * 32);
        int p = ks & 1;
        __half2 s0v = H2(sc0[p]), t0v = H2(tc0[p]), s8v = H2(sc8[p]), t8v = H2(tc8[p]);
#pragma unroll
        for (int mt = 0; mt < 4; mt++) {
            H2(a[mt][0]) = __hfma2_relu(H2(a[mt][0]), s0v, t0v);
            H2(a[mt][1]) = __hfma2_relu(H2(a[mt][1]), s0v, t0v);
            H2(a[mt][2]) = __hfma2_relu(H2(a[mt][2]), s8v, t8v);
            H2(a[mt][3]) = __hfma2_relu(H2(a[mt][3]), s8v, t8v);
        }
        int base = ((nw * 8 + ks) * 4) * 32 + lid;   // dense per-LDG fragments
        uint4 b0 = Bf[base], b1 = Bf[base + 32];
#pragma unroll
        for (int mt = 0; mt < 4; mt++) {
            mmaf16(acc[mt][0], a[mt], b0.x, b0.y);
            mmaf16(acc[mt][1], a[mt], b0.z, b0.w);
            mmaf16(acc[mt][2], a[mt], b1.x, b1.y);
            mmaf16(acc[mt][3], a[mt], b1.z, b1.w);
        }
        uint4 b2 = Bf[base + 64], b3 = Bf[base + 96];
#pragma unroll
        for (int mt = 0; mt < 4; mt++) {
            mmaf16(acc[mt][0], a[mt], b2.x, b2.y);
            mmaf16(acc[mt][1], a[mt], b2.z, b2.w);
            mmaf16(acc[mt][2], a[mt], b3.x, b3.y);
            mmaf16(acc[mt][3], a[mt], b3.z, b3.w);
        }
    }
    __syncthreads();   // A done -> staging (stride 72)

    __half* st = (__half*)Ab;
#pragma unroll
    for (int mt = 0; mt < 4; mt++) {
        int g = mb + mt * 16 + (lid >> 2);
#pragma unroll
        for (int nt = 0; nt < 4; nt++) {
            int col = nb + nt * 8 + (lid & 3) * 2;
            *(__half2*)(st + g * 72 + col)       = __float22half2_rn(make_float2(acc[mt][nt][0], acc[mt][nt][1]));
            *(__half2*)(st + (g + 8) * 72 + col) = __float22half2_rn(make_float2(acc[mt][nt][2], acc[mt][nt][3]));
        }
    }
#pragma unroll
    for (int nt = 0; nt < 4; nt++)
#pragma unroll
        for (int j = 0; j < 2; j++) {
            float v = 0.f, q = 0.f;
#pragma unroll
            for (int mt = 0; mt < 4; mt++) {
                float a = acc[mt][nt][j], b = acc[mt][nt][j + 2];
                v += a + b;
                q = fmaf(a, a, q); q = fmaf(b, b, q);
            }
            red4(v); red4(q);
            if (lid < 4) {
                int col = nb + nt * 8 + lid * 2 + j;
                atomicAdd(&s_red[col], v);
                atomicAdd(&s_red[64 + col], q);
            }
        }
    __syncthreads();
    {   // y1 write (permuted rows), one row (128B) per thread
        size_t mm = m0 + tid;
        int bb = (int)(mm / 196);
        int rem = (int)(mm - (size_t)bb * 196);
        int OH = rem / 14, OW = rem - OH * 14;
        __half* dst = g_y1h + (((size_t)bb * 7 + (OH >> 1)) * 7 + (OW >> 1)) * 256 +
                      ((((OH & 1) << 1) | (OW & 1)) << 6);
        const __half* srow = st + tid * 72;
#pragma unroll
        for (int q = 0; q < 8; q++) ((uint4*)dst)[q] = ((const uint4*)srow)[q];
    }
    if (tid < 64) {
        atomicAdd(&g_stats[64 + tid], (double)s_red[tid]);
        atomicAdd(&g_stats[128 + tid], (double)s_red[64 + tid]);
    }
}

// ======================= conv2: HMMA GEMM  M=401408(x128), N=128(2x64), K=256 =======================
#define A2STR 264
#define A2STEP (16 * A2STR * 2)
#define SM2_BYTES (128 * A2STR * 2 + 512)
__global__ void __launch_bounds__(128) conv2_k() {
    extern __shared__ __align__(16) __half Ab2[];
    float* s_red = (float*)(Ab2 + 128 * A2STR);
    int tid = threadIdx.x, wid = tid >> 5, lid = tid & 31;
    size_t m0 = (size_t)blockIdx.x * 128;
    int nh = blockIdx.y;
    const __half* Asrc = g_y1h + m0 * 256;
#pragma unroll
    for (int i = 0; i < 32; i++) {
        int idx = tid + i * 128;
        int row = idx >> 5, c16 = idx & 31;
        cpasync16(s2u(&Ab2[row * A2STR + c16 * 8]), Asrc + row * 256 + c16 * 8);
    }
    CP_COMMIT;
    if (tid < 128) s_red[tid] = 0.f;
    // packed BN1 scales + hoisted shuffles (4 variants)
    uint32_t spk, tpk;
    { __half2 sp = __floats2half2_rn(g_s1[2 * lid], g_s1[2 * lid + 1]);
      __half2 tp = __floats2half2_rn(g_t1[2 * lid], g_t1[2 * lid + 1]);
      spk = *(uint32_t*)&sp; tpk = *(uint32_t*)&tp; }
    uint32_t sc0[4], tc0[4], sc8[4], tc8[4];
#pragma unroll
    for (int v = 0; v < 4; v++) {
        int i0 = v * 8 + (lid & 3);
        sc0[v] = __shfl_sync(0xFFFFFFFFu, spk, i0);     tc0[v] = __shfl_sync(0xFFFFFFFFu, tpk, i0);
        sc8[v] = __shfl_sync(0xFFFFFFFFu, spk, i0 + 4); tc8[v] = __shfl_sync(0xFFFFFFFFu, tpk, i0 + 4);
    }
    int mw = wid & 1, nw = wid >> 1;
    int mb = mw * 64, nb = nw * 32;
    float acc[4][4][4];
#pragma unroll
    for (int i = 0; i < 4; i++)
#pragma unroll
        for (int j = 0; j < 4; j++)
#pragma unroll
            for (int q = 0; q < 4; q++) acc[i][j][q] = 0.f;
    const uint4* Bf = (const uint4*)g_B2f;
    uint32_t aB = s2u(&Ab2[(mb + (lid & 15)) * A2STR + (lid >> 4) * 8]);
    CP_WAIT0;
    __syncthreads();
#pragma unroll
    for (int ks = 0; ks < 16; ks++) {
        uint32_t a[4][4];
#pragma unroll
        for (int mt = 0; mt < 4; mt++) ldm4(a[mt], aB + mt * A2STEP + ks * 32);
        int p = ks & 3;
        __half2 s0v = H2(sc0[p]), t0v = H2(tc0[p]), s8v = H2(sc8[p]), t8v = H2(tc8[p]);
#pragma unroll
        for (int mt = 0; mt < 4; mt++) {
            H2(a[mt][0]) = __hfma2_relu(H2(a[mt][0]), s0v, t0v);
            H2(a[mt][1]) = __hfma2_relu(H2(a[mt][1]), s0v, t0v);
            H2(a[mt][2]) = __hfma2_relu(H2(a[mt][2]), s8v, t8v);
            H2(a[mt][3]) = __hfma2_relu(H2(a[mt][3]), s8v, t8v);
        }
        int base = ((((nh * 2 + nw) * 16) + ks) * 4) * 32 + lid;
        uint4 b0 = Bf[base], b1 = Bf[base + 32];
#pragma unroll
        for (int mt = 0; mt < 4; mt++) {
            mmaf16(acc[mt][0], a[mt], b0.x, b0.y);
            mmaf16(acc[mt][1], a[mt], b0.z, b0.w);
            mmaf16(acc[mt][2], a[mt], b1.x, b1.y);
            mmaf16(acc[mt][3], a[mt], b1.z, b1.w);
        }
        uint4 b2 = Bf[base + 64], b3 = Bf[base + 96];
#pragma unroll
        for (int mt = 0; mt < 4; mt++) {
            mmaf16(acc[mt][0], a[mt], b2.x, b2.y);
            mmaf16(acc[mt][1], a[mt], b2.z, b2.w);
            mmaf16(acc[mt][2], a[mt], b3.x, b3.y);
            mmaf16(acc[mt][3], a[mt], b3.z, b3.w);
        }
    }
    __syncthreads();

    __half* st = (__half*)Ab2;   // staging stride 72
#pragma unroll
    for (int mt = 0; mt < 4; mt++) {
        int g = mb + mt * 16 + (lid >> 2);
#pragma unroll
        for (int nt = 0; nt < 4; nt++) {
            int col = nb + nt * 8 + (lid & 3) * 2;
            *(__half2*)(st + g * 72 + col)       = __float22half2_rn(make_float2(acc[mt][nt][0], acc[mt][nt][1]));
            *(__half2*)(st + (g + 8) * 72 + col) = __float22half2_rn(make_float2(acc[mt][nt][2], acc[mt][nt][3]));
        }
    }
#pragma unroll
    for (int nt = 0; nt < 4; nt++)
#pragma unroll
        for (int j = 0; j < 2; j++) {
            float v = 0.f, q = 0.f;
#pragma unroll
            for (int mt = 0; mt < 4; mt++) {
                float a = acc[mt][nt][j], b = acc[mt][nt][j + 2];
                v += a + b;
                q = fmaf(a, a, q); q = fmaf(b, b, q);
            }
            red4(v); red4(q);
            if (lid < 4) {
                int col = nb + nt * 8 + lid * 2 + j;
                atomicAdd(&s_red[col], v);
                atomicAdd(&s_red[64 + col], q);
            }
        }
    __syncthreads();
    {   // y2 write row-major, this CTA's FULL 64-col half (8 x uint4 = 64 halves)
        __half* dst = g_y2h + (m0 + tid) * 128 + nh * 64;
        const __half* srow = st + tid * 72;
#pragma unroll
        for (int q = 0; q < 8; q++) ((uint4*)dst)[q] = ((const uint4*)srow)[q];
    }
    if (tid < 64) {
        atomicAdd(&g_stats[192 + nh * 64 + tid], (double)s_red[tid]);
        atomicAdd(&g_stats[320 + nh * 64 + tid], (double)s_red[64 + tid]);
    }
}

// ---------------- final: BN2+ReLU, avg-pool 49, FC 128->10 ----------------
__global__ void __launch_bounds__(128) final_k(const float* __restrict__ wfc,
                                               const float* __restrict__ bfc,
                                               float* __restrict__ out) {
    __shared__ float f[128];
    int b = blockIdx.x, tid = threadIdx.x;
    const __half* y = g_y2h + (size_t)b * 49 * 128;
    float s = g_s2[tid], t = g_t2[tid];
    float acc = 0.f;
#pragma unroll 7
    for (int p = 0; p < 49; p++) acc += fmaxf(fmaf(__half2float(y[p * 128 + tid]), s, t), 0.f);
    f[tid] = acc * (1.f / 49.f);
    __syncthreads();
    if (tid < 10) {
        float o = bfc[tid];
        const float* wr = wfc + tid * 128;
#pragma unroll 8
        for (int c2 = 0; c2 < 128; c2++) o = fmaf(f[c2], wr[c2], o);
        out[(size_t)b * 10 + tid] = o;
    }
}

// ---------------- launch ----------------
extern "C" void kernel_launch(void* const* d_in, const int* in_sizes, int n_in,
                              void* d_out, int out_size) {
    const float* x   = (const float*)d_in[0];
    const float* w0  = (const float*)d_in[1];
    const float* g0  = (const float*)d_in[3];
    const float* be0 = (const float*)d_in[4];
    const float* w1  = (const float*)d_in[5];
    const float* g1  = (const float*)d_in[7];
    const float* be1 = (const float*)d_in[8];
    const float* w2  = (const float*)d_in[9];
    const float* g2  = (const float*)d_in[11];
    const float* be2 = (const float*)d_in[12];
    const float* wfc = (const float*)d_in[13];
    const float* bfc = (const float*)d_in[14];
    float* out = (float*)d_out;

    cudaFuncSetAttribute(conv2_k, cudaFuncAttributeMaxDynamicSharedMemorySize, SM2_BYTES);

    prep_k<<<128, 256>>>(w1, w2);
    conv0_k<<<BATCH, 256>>>(x, w0);
    scale0_k<<<1, 32>>>(g0, be0);
    conv1_k<<<12544, 128>>>();
    scale1_k<<<1, 64>>>(g1, be1);
    conv2_k<<<dim3(3136, 2), 128, SM2_BYTES>>>();
    scale2_k<<<1, 128>>>(g2, be2);
    final_k<<<BATCH, 128>>>(wfc, bfc, out);
}

// round 14
// speedup vs baseline: 3.4398x; 1.0374x over previous
#include <cuda_runtime.h>
#include <cuda_fp16.h>
#include <cstdint>

#define BATCH 8192

// ---------------- scratch ----------------
__device__ __align__(16) __half g_y0h[(size_t)BATCH * 196 * 128];   // [b][14][14][khw(4)][c(32)] raw conv0
__device__ __align__(16) __half g_y1h[(size_t)BATCH * 49 * 256];    // [b][7][7][khw(4)][c(64)]   raw conv1
__device__ __align__(16) __half g_y2h[(size_t)BATCH * 49 * 128];    // [b][49][c(128)]            raw conv2
__device__ double g_stats[448];
__device__ float  g_s0[32], g_t0[32], g_s1[64], g_t1[64], g_s2[128], g_t2[128];
// B operands, fragment order, DENSE per-LDG, hi-only:
// B1f: [nw(2)][ks(8)][h16(2)][lane(32)][8 halves]            (16KB)
// B2f: [nh(2)][nw(2)][ks(16)][h16(2)][lane(32)][8 halves]    (64KB)
__device__ __align__(16) __half g_B1f[8192];
__device__ __align__(16) __half g_B2f[32768];

// ---------------- helpers ----------------
#define H2(r) (*reinterpret_cast<__half2*>(&(r)))
__device__ __forceinline__ uint32_t s2u(const void* p) {
    uint32_t a;
    asm("{ .reg .u64 t; cvta.to.shared.u64 t, %1; cvt.u32.u64 %0, t; }" : "=r"(a) : "l"(p));
    return a;
}
__device__ __forceinline__ void ldm4(uint32_t* r, uint32_t addr) {
    asm volatile("ldmatrix.sync.aligned.m8n8.x4.shared.b16 {%0,%1,%2,%3}, [%4];"
                 : "=r"(r[0]), "=r"(r[1]), "=r"(r[2]), "=r"(r[3]) : "r"(addr));
}
__device__ __forceinline__ void mmaf16(float* d, const uint32_t* a, uint32_t b0, uint32_t b1) {
    asm volatile("mma.sync.aligned.m16n8k16.row.col.f32.f16.f16.f32 "
                 "{%0,%1,%2,%3}, {%4,%5,%6,%7}, {%8,%9}, {%0,%1,%2,%3};"
                 : "+f"(d[0]), "+f"(d[1]), "+f"(d[2]), "+f"(d[3])
                 : "r"(a[0]), "r"(a[1]), "r"(a[2]), "r"(a[3]), "r"(b0), "r"(b1));
}
__device__ __forceinline__ void red4(float& v) {
    v += __shfl_xor_sync(0xFFFFFFFFu, v, 4);
    v += __shfl_xor_sync(0xFFFFFFFFu, v, 8);
    v += __shfl_xor_sync(0xFFFFFFFFu, v, 16);
}
__device__ __forceinline__ void cpasync16(uint32_t dst, const void* src) {
    asm volatile("cp.async.cg.shared.global [%0], [%1], 16;" :: "r"(dst), "l"(src));
}
#define CP_COMMIT asm volatile("cp.async.commit_group;" ::: "memory")
#define CP_WAIT0  asm volatile("cp.async.wait_group 0;" ::: "memory")

// ---------------- prep: zero stats, dense fragment-order hi-only B images ----------------
__global__ void prep_k(const float* __restrict__ w1, const float* __restrict__ w2) {
    int t0 = blockIdx.x * blockDim.x + threadIdx.x, stride = blockDim.x * gridDim.x;
    for (int i = t0; i < 448; i += stride) g_stats[i] = 0.0;
    for (int i = t0; i < 8192; i += stride) {
        int h = i & 1, reg = (i >> 1) & 1, t = (i >> 2) & 1, lane = (i >> 3) & 31;
        int h16 = (i >> 8) & 1, ks = (i >> 9) & 7, nw = (i >> 12) & 1;
        int n = nw * 32 + h16 * 16 + t * 8 + (lane >> 2);
        int k = ks * 16 + (lane & 3) * 2 + reg * 8 + h;
        int khw = k >> 5, c = k & 31;
        float w = w1[((n * 32 + c) * 2 + (khw >> 1)) * 2 + (khw & 1)];
        g_B1f[i] = __float2half_rn(w);
    }
    for (int i = t0; i < 32768; i += stride) {
        int h = i & 1, reg = (i >> 1) & 1, t = (i >> 2) & 1, lane = (i >> 3) & 31;
        int h16 = (i >> 8) & 1, ks = (i >> 9) & 15, nw = (i >> 13) & 1, nh = (i >> 14) & 1;
        int n = nh * 64 + nw * 32 + h16 * 16 + t * 8 + (lane >> 2);
        int k = ks * 16 + (lane & 3) * 2 + reg * 8 + h;
        int khw = k >> 6, c = k & 63;
        float w = w2[((n * 64 + c) * 2 + (khw >> 1)) * 2 + (khw & 1)];
        g_B2f[i] = __float2half_rn(w);
    }
}

// ---------------- conv0: 1->32, 3x3 SAME, raw fp16 output + exact fp32 stats ----------------
__global__ void __launch_bounds__(256) conv0_k(const float* __restrict__ x, const float* __restrict__ w0) {
    __shared__ float sx[900];
    __shared__ float rs[256], rq[256];
    int b = blockIdx.x, tid = threadIdx.x;
    for (int i = tid; i < 900; i += 256) sx[i] = 0.f;
    __syncthreads();
    const float* xb = x + (size_t)b * 784;
    for (int i = tid; i < 784; i += 256) {
        int r = i / 28, c = i - r * 28;
        sx[(r + 1) * 30 + c + 1] = xb[i];
    }
    __syncthreads();
    int c = tid & 31, p = tid >> 5;
    float w[9];
#pragma unroll
    for (int i = 0; i < 9; i++) w[i] = w0[c * 9 + i];
    float sum = 0.f, sq = 0.f;
    __half* outb = g_y0h + (size_t)b * (196 * 128);
    for (int it = 0; it < 98; it++) {
        int pix = it * 8 + p;
        int OH = pix / 28, OW = pix - OH * 28;
        const float* s = &sx[OH * 30 + OW];
        float acc = w[0] * s[0];
        acc = fmaf(w[1], s[1], acc);  acc = fmaf(w[2], s[2], acc);
        acc = fmaf(w[3], s[30], acc); acc = fmaf(w[4], s[31], acc); acc = fmaf(w[5], s[32], acc);
        acc = fmaf(w[6], s[60], acc); acc = fmaf(w[7], s[61], acc); acc = fmaf(w[8], s[62], acc);
        int oh = OH >> 1, ow = OW >> 1, khw = ((OH & 1) << 1) | (OW & 1);
        outb[(size_t)((oh * 14 + ow) * 4 + khw) * 32 + c] = __float2half_rn(acc);
        sum += acc;
        sq = fmaf(acc, acc, sq);
    }
    rs[tid] = sum; rq[tid] = sq;
    __syncthreads();
    if (p == 0) {
        float S = 0.f, Q = 0.f;
#pragma unroll
        for (int j = 0; j < 8; j++) { S += rs[j * 32 + c]; Q += rq[j * 32 + c]; }
        atomicAdd(&g_stats[c], (double)S);
        atomicAdd(&g_stats[32 + c], (double)Q);
    }
}

// ---------------- scale kernels ----------------
__global__ void scale0_k(const float* __restrict__ g, const float* __restrict__ be) {
    int c = threadIdx.x;
    const double invN = 1.0 / 6422528.0;
    double mean = g_stats[c] * invN;
    double var  = g_stats[32 + c] * invN - mean * mean;
    double s = (double)g[c] / sqrt(var + 1e-5);
    g_s0[c] = (float)s; g_t0[c] = (float)((double)be[c] - mean * s);
}
__global__ void scale1_k(const float* __restrict__ g, const float* __restrict__ be) {
    int c = threadIdx.x;
    const double invN = 1.0 / 1605632.0;
    double mean = g_stats[64 + c] * invN;
    double var  = g_stats[128 + c] * invN - mean * mean;
    double s = (double)g[c] / sqrt(var + 1e-5);
    g_s1[c] = (float)s; g_t1[c] = (float)((double)be[c] - mean * s);
}
__global__ void scale2_k(const float* __restrict__ g, const float* __restrict__ be) {
    int c = threadIdx.x;
    const double invN = 1.0 / 401408.0;
    double mean = g_stats[192 + c] * invN;
    double var  = g_stats[320 + c] * invN - mean * mean;
    double s = (double)g[c] / sqrt(var + 1e-5);
    g_s2[c] = (float)s; g_t2[c] = (float)((double)be[c] - mean * s);
}

// ======================= conv1: HMMA GEMM  M=1605632(x128), N=64, K=128 =======================
// 256 threads, warps 4(m)x2(n), warp tile 32x32, hi-only weights. A single-shot cp.async [128][136].
#define A1STR 136
#define A1STEP (16 * A1STR * 2)
__global__ void __launch_bounds__(256, 3) conv1_k() {
    __shared__ __align__(16) __half Ab[128 * A1STR];
    __shared__ float s_red[128];
    int tid = threadIdx.x, wid = tid >> 5, lid = tid & 31;
    size_t m0 = (size_t)blockIdx.x * 128;
    const __half* Asrc = g_y0h + m0 * 128;
#pragma unroll
    for (int i = 0; i < 8; i++) {
        int idx = tid + i * 256;
        int row = idx >> 4, c16 = idx & 15;
        cpasync16(s2u(&Ab[row * A1STR + c16 * 8]), Asrc + row * 128 + c16 * 8);
    }
    CP_COMMIT;
    if (tid < 128) s_red[tid] = 0.f;
    // packed BN scales + hoisted shuffles (2 variants: ks even/odd)
    int ch0 = (lid & 15) * 2;
    uint32_t spk, tpk;
    { __half2 sp = __floats2half2_rn(g_s0[ch0], g_s0[ch0 + 1]);
      __half2 tp = __floats2half2_rn(g_t0[ch0], g_t0[ch0 + 1]);
      spk = *(uint32_t*)&sp; tpk = *(uint32_t*)&tp; }
    uint32_t sc0[2], tc0[2], sc8[2], tc8[2];
#pragma unroll
    for (int v = 0; v < 2; v++) {
        int i0 = v * 8 + (lid & 3);
        sc0[v] = __shfl_sync(0xFFFFFFFFu, spk, i0);     tc0[v] = __shfl_sync(0xFFFFFFFFu, tpk, i0);
        sc8[v] = __shfl_sync(0xFFFFFFFFu, spk, i0 + 4); tc8[v] = __shfl_sync(0xFFFFFFFFu, tpk, i0 + 4);
    }
    int mw = wid & 3, nw = wid >> 2;
    int mb = mw * 32, nb = nw * 32;
    float acc[2][4][4];
#pragma unroll
    for (int i = 0; i < 2; i++)
#pragma unroll
        for (int j = 0; j < 4; j++)
#pragma unroll
            for (int q = 0; q < 4; q++) acc[i][j][q] = 0.f;
    const uint4* Bf = (const uint4*)g_B1f;
    uint32_t aB = s2u(&Ab[(mb + (lid & 15)) * A1STR + (lid >> 4) * 8]);
    CP_WAIT0;
    __syncthreads();
#pragma unroll
    for (int ks = 0; ks < 8; ks++) {
        int base = ((nw * 8 + ks) * 2) * 32 + lid;   // dense hi-only fragments
        uint4 b0 = Bf[base], b1 = Bf[base + 32];
        uint32_t a[2][4];
#pragma unroll
        for (int mt = 0; mt < 2; mt++) ldm4(a[mt], aB + mt * A1STEP + ks * 32);
        int p = ks & 1;
        __half2 s0v = H2(sc0[p]), t0v = H2(tc0[p]), s8v = H2(sc8[p]), t8v = H2(tc8[p]);
#pragma unroll
        for (int mt = 0; mt < 2; mt++) {
            H2(a[mt][0]) = __hfma2_relu(H2(a[mt][0]), s0v, t0v);
            H2(a[mt][1]) = __hfma2_relu(H2(a[mt][1]), s0v, t0v);
            H2(a[mt][2]) = __hfma2_relu(H2(a[mt][2]), s8v, t8v);
            H2(a[mt][3]) = __hfma2_relu(H2(a[mt][3]), s8v, t8v);
        }
#pragma unroll
        for (int mt = 0; mt < 2; mt++) {
            mmaf16(acc[mt][0], a[mt], b0.x, b0.y);
            mmaf16(acc[mt][1], a[mt], b0.z, b0.w);
            mmaf16(acc[mt][2], a[mt], b1.x, b1.y);
            mmaf16(acc[mt][3], a[mt], b1.z, b1.w);
        }
    }
    __syncthreads();   // A done -> staging (stride 72)

    __half* st = (__half*)Ab;
#pragma unroll
    for (int mt = 0; mt < 2; mt++) {
        int g = mb + mt * 16 + (lid >> 2);
#pragma unroll
        for (int nt = 0; nt < 4; nt++) {
            int col = nb + nt * 8 + (lid & 3) * 2;
            *(__half2*)(st + g * 72 + col)       = __float22half2_rn(make_float2(acc[mt][nt][0], acc[mt][nt][1]));
            *(__half2*)(st + (g + 8) * 72 + col) = __float22half2_rn(make_float2(acc[mt][nt][2], acc[mt][nt][3]));
        }
    }
#pragma unroll
    for (int nt = 0; nt < 4; nt++)
#pragma unroll
        for (int j = 0; j < 2; j++) {
            float v = 0.f, q = 0.f;
#pragma unroll
            for (int mt = 0; mt < 2; mt++) {
                float a = acc[mt][nt][j], b = acc[mt][nt][j + 2];
                v += a + b;
                q = fmaf(a, a, q); q = fmaf(b, b, q);
            }
            red4(v); red4(q);
            if (lid < 4) {
                int col = nb + nt * 8 + lid * 2 + j;
                atomicAdd(&s_red[col], v);
                atomicAdd(&s_red[64 + col], q);
            }
        }
    __syncthreads();
    {   // y1 write (permuted rows), 2 threads per row, 64B each
        int r = tid >> 1, h = tid & 1;
        size_t mm = m0 + r;
        int bb = (int)(mm / 196);
        int rem = (int)(mm - (size_t)bb * 196);
        int OH = rem / 14, OW = rem - OH * 14;
        __half* dst = g_y1h + (((size_t)bb * 7 + (OH >> 1)) * 7 + (OW >> 1)) * 256 +
                      ((((OH & 1) << 1) | (OW & 1)) << 6) + h * 32;
        const __half* srow = st + r * 72 + h * 32;
#pragma unroll
        for (int q = 0; q < 4; q++) ((uint4*)dst)[q] = ((const uint4*)srow)[q];
    }
    if (tid < 64) {
        atomicAdd(&g_stats[64 + tid], (double)s_red[tid]);
        atomicAdd(&g_stats[128 + tid], (double)s_red[64 + tid]);
    }
}

// ======================= conv2: HMMA GEMM  M=401408(x128), N=128(2x64), K=256 =======================
#define A2STR 264
#define A2STEP (16 * A2STR * 2)
#define SM2_BYTES (128 * A2STR * 2 + 512)
__global__ void __launch_bounds__(256, 3) conv2_k() {
    extern __shared__ __align__(16) __half Ab2[];
    float* s_red = (float*)(Ab2 + 128 * A2STR);
    int tid = threadIdx.x, wid = tid >> 5, lid = tid & 31;
    size_t m0 = (size_t)blockIdx.x * 128;
    int nh = blockIdx.y;
    const __half* Asrc = g_y1h + m0 * 256;
#pragma unroll
    for (int i = 0; i < 16; i++) {
        int idx = tid + i * 256;
        int row = idx >> 5, c16 = idx & 31;
        cpasync16(s2u(&Ab2[row * A2STR + c16 * 8]), Asrc + row * 256 + c16 * 8);
    }
    CP_COMMIT;
    if (tid < 128) s_red[tid] = 0.f;
    // packed BN1 scales + hoisted shuffles (4 variants)
    uint32_t spk, tpk;
    { __half2 sp = __floats2half2_rn(g_s1[2 * lid], g_s1[2 * lid + 1]);
      __half2 tp = __floats2half2_rn(g_t1[2 * lid], g_t1[2 * lid + 1]);
      spk = *(uint32_t*)&sp; tpk = *(uint32_t*)&tp; }
    uint32_t sc0[4], tc0[4], sc8[4], tc8[4];
#pragma unroll
    for (int v = 0; v < 4; v++) {
        int i0 = v * 8 + (lid & 3);
        sc0[v] = __shfl_sync(0xFFFFFFFFu, spk, i0);     tc0[v] = __shfl_sync(0xFFFFFFFFu, tpk, i0);
        sc8[v] = __shfl_sync(0xFFFFFFFFu, spk, i0 + 4); tc8[v] = __shfl_sync(0xFFFFFFFFu, tpk, i0 + 4);
    }
    int mw = wid & 3, nw = wid >> 2;
    int mb = mw * 32, nb = nw * 32;
    float acc[2][4][4];
#pragma unroll
    for (int i = 0; i < 2; i++)
#pragma unroll
        for (int j = 0; j < 4; j++)
#pragma unroll
            for (int q = 0; q < 4; q++) acc[i][j][q] = 0.f;
    const uint4* Bf = (const uint4*)g_B2f;
    uint32_t aB = s2u(&Ab2[(mb + (lid & 15)) * A2STR + (lid >> 4) * 8]);
    CP_WAIT0;
    __syncthreads();
#pragma unroll
    for (int ks = 0; ks < 16; ks++) {
        int base = ((((nh * 2 + nw) * 16) + ks) * 2) * 32 + lid;
        uint4 b0 = Bf[base], b1 = Bf[base + 32];
        uint32_t a[2][4];
#pragma unroll
        for (int mt = 0; mt < 2; mt++) ldm4(a[mt], aB + mt * A2STEP + ks * 32);
        int p = ks & 3;
        __half2 s0v = H2(sc0[p]), t0v = H2(tc0[p]), s8v = H2(sc8[p]), t8v = H2(tc8[p]);
#pragma unroll
        for (int mt = 0; mt < 2; mt++) {
            H2(a[mt][0]) = __hfma2_relu(H2(a[mt][0]), s0v, t0v);
            H2(a[mt][1]) = __hfma2_relu(H2(a[mt][1]), s0v, t0v);
            H2(a[mt][2]) = __hfma2_relu(H2(a[mt][2]), s8v, t8v);
            H2(a[mt][3]) = __hfma2_relu(H2(a[mt][3]), s8v, t8v);
        }
#pragma unroll
        for (int mt = 0; mt < 2; mt++) {
            mmaf16(acc[mt][0], a[mt], b0.x, b0.y);
            mmaf16(acc[mt][1], a[mt], b0.z, b0.w);
            mmaf16(acc[mt][2], a[mt], b1.x, b1.y);
            mmaf16(acc[mt][3], a[mt], b1.z, b1.w);
        }
    }
    __syncthreads();

    __half* st = (__half*)Ab2;   // staging stride 72
#pragma unroll
    for (int mt = 0; mt < 2; mt++) {
        int g = mb + mt * 16 + (lid >> 2);
#pragma unroll
        for (int nt = 0; nt < 4; nt++) {
            int col = nb + nt * 8 + (lid & 3) * 2;
            *(__half2*)(st + g * 72 + col)       = __float22half2_rn(make_float2(acc[mt][nt][0], acc[mt][nt][1]));
            *(__half2*)(st + (g + 8) * 72 + col) = __float22half2_rn(make_float2(acc[mt][nt][2], acc[mt][nt][3]));
        }
    }
#pragma unroll
    for (int nt = 0; nt < 4; nt++)
#pragma unroll
        for (int j = 0; j < 2; j++) {
            float v = 0.f, q = 0.f;
#pragma unroll
            for (int mt = 0; mt < 2; mt++) {
                float a = acc[mt][nt][j], b = acc[mt][nt][j + 2];
                v += a + b;
                q = fmaf(a, a, q); q = fmaf(b, b, q);
            }
            red4(v); red4(q);
            if (lid < 4) {
                int col = nb + nt * 8 + lid * 2 + j;
                atomicAdd(&s_red[col], v);
                atomicAdd(&s_red[64 + col], q);
            }
        }
    __syncthreads();
    {   // y2 write row-major, this CTA's 64-col half; 2 threads per row, 64B each
        int r = tid >> 1, h = tid & 1;
        __half* dst = g_y2h + (m0 + r) * 128 + nh * 64 + h * 32;
        const __half* srow = st + r * 72 + h * 32;
#pragma unroll
        for (int q = 0; q < 4; q++) ((uint4*)dst)[q] = ((const uint4*)srow)[q];
    }
    if (tid < 64) {
        atomicAdd(&g_stats[192 + nh * 64 + tid], (double)s_red[tid]);
        atomicAdd(&g_stats[320 + nh * 64 + tid], (double)s_red[64 + tid]);
    }
}

// ---------------- final: BN2+ReLU, avg-pool 49, FC 128->10 ----------------
__global__ void __launch_bounds__(128) final_k(const float* __restrict__ wfc,
                                               const float* __restrict__ bfc,
                                               float* __restrict__ out) {
    __shared__ float f[128];
    int b = blockIdx.x, tid = threadIdx.x;
    const __half* y = g_y2h + (size_t)b * 49 * 128;
    float s = g_s2[tid], t = g_t2[tid];
    float acc = 0.f;
#pragma unroll 7
    for (int p = 0; p < 49; p++) acc += fmaxf(fmaf(__half2float(y[p * 128 + tid]), s, t), 0.f);
    f[tid] = acc * (1.f / 49.f);
    __syncthreads();
    if (tid < 10) {
        float o = bfc[tid];
        const float* wr = wfc + tid * 128;
#pragma unroll 8
        for (int c2 = 0; c2 < 128; c2++) o = fmaf(f[c2], wr[c2], o);
        out[(size_t)b * 10 + tid] = o;
    }
}

// ---------------- launch ----------------
extern "C" void kernel_launch(void* const* d_in, const int* in_sizes, int n_in,
                              void* d_out, int out_size) {
    const float* x   = (const float*)d_in[0];
    const float* w0  = (const float*)d_in[1];
    const float* g0  = (const float*)d_in[3];
    const float* be0 = (const float*)d_in[4];
    const float* w1  = (const float*)d_in[5];
    const float* g1  = (const float*)d_in[7];
    const float* be1 = (const float*)d_in[8];
    const float* w2  = (const float*)d_in[9];
    const float* g2  = (const float*)d_in[11];
    const float* be2 = (const float*)d_in[12];
    const float* wfc = (const float*)d_in[13];
    const float* bfc = (const float*)d_in[14];
    float* out = (float*)d_out;

    cudaFuncSetAttribute(conv2_k, cudaFuncAttributeMaxDynamicSharedMemorySize, SM2_BYTES);

    prep_k<<<128, 256>>>(w1, w2);
    conv0_k<<<BATCH, 256>>>(x, w0);
    scale0_k<<<1, 32>>>(g0, be0);
    conv1_k<<<12544, 256>>>();
    scale1_k<<<1, 64>>>(g1, be1);
    conv2_k<<<dim3(3136, 2), 256, SM2_BYTES>>>();
    scale2_k<<<1, 128>>>(g2, be2);
    final_k<<<BATCH, 128>>>(wfc, bfc, out);
}

// round 15
// speedup vs baseline: 3.7804x; 1.0990x over previous
#include <cuda_runtime.h>
#include <cuda_fp16.h>
#include <cstdint>

#define BATCH 8192

// ---------------- scratch ----------------
__device__ __align__(16) __half g_y1h[(size_t)BATCH * 49 * 256];    // [b][7][7][khw(4)][c(64)]   raw conv1
__device__ __align__(16) __half g_y2h[(size_t)BATCH * 49 * 128];    // [b][49][c(128)]            raw conv2
__device__ double g_stats[448];
__device__ double g_xstat[54];     // S[9] | C45 (second moments of padded 3x3 patches of x)
__device__ float  g_s0[32], g_t0[32], g_s1[64], g_t1[64], g_s2[128], g_t2[128];
// B operands, fragment order, DENSE per-LDG, hi-only:
// B1f: [nw(2)][ks(8)][h16(2)][lane(32)][8 halves]            (16KB)
// B2f: [nh(2)][nw(2)][ks(16)][h16(2)][lane(32)][8 halves]    (64KB)
__device__ __align__(16) __half g_B1f[8192];
__device__ __align__(16) __half g_B2f[32768];

// ---------------- helpers ----------------
#define H2(r) (*reinterpret_cast<__half2*>(&(r)))
__device__ __forceinline__ uint32_t s2u(const void* p) {
    uint32_t a;
    asm("{ .reg .u64 t; cvta.to.shared.u64 t, %1; cvt.u32.u64 %0, t; }" : "=r"(a) : "l"(p));
    return a;
}
__device__ __forceinline__ void ldm4(uint32_t* r, uint32_t addr) {
    asm volatile("ldmatrix.sync.aligned.m8n8.x4.shared.b16 {%0,%1,%2,%3}, [%4];"
                 : "=r"(r[0]), "=r"(r[1]), "=r"(r[2]), "=r"(r[3]) : "r"(addr));
}
__device__ __forceinline__ void mmaf16(float* d, const uint32_t* a, uint32_t b0, uint32_t b1) {
    asm volatile("mma.sync.aligned.m16n8k16.row.col.f32.f16.f16.f32 "
                 "{%0,%1,%2,%3}, {%4,%5,%6,%7}, {%8,%9}, {%0,%1,%2,%3};"
                 : "+f"(d[0]), "+f"(d[1]), "+f"(d[2]), "+f"(d[3])
                 : "r"(a[0]), "r"(a[1]), "r"(a[2]), "r"(a[3]), "r"(b0), "r"(b1));
}
__device__ __forceinline__ void red4(float& v) {
    v += __shfl_xor_sync(0xFFFFFFFFu, v, 4);
    v += __shfl_xor_sync(0xFFFFFFFFu, v, 8);
    v += __shfl_xor_sync(0xFFFFFFFFu, v, 16);
}
__device__ __forceinline__ void cpasync16(uint32_t dst, const void* src) {
    asm volatile("cp.async.cg.shared.global [%0], [%1], 16;" :: "r"(dst), "l"(src));
}
#define CP_COMMIT asm volatile("cp.async.commit_group;" ::: "memory")
#define CP_WAIT0  asm volatile("cp.async.wait_group 0;" ::: "memory")

// ---------------- prep: zero stats, dense fragment-order hi-only B images ----------------
__global__ void prep_k(const float* __restrict__ w1, const float* __restrict__ w2) {
    int t0 = blockIdx.x * blockDim.x + threadIdx.x, stride = blockDim.x * gridDim.x;
    for (int i = t0; i < 448; i += stride) g_stats[i] = 0.0;
    for (int i = t0; i < 54; i += stride) g_xstat[i] = 0.0;
    for (int i = t0; i < 8192; i += stride) {
        int h = i & 1, reg = (i >> 1) & 1, t = (i >> 2) & 1, lane = (i >> 3) & 31;
        int h16 = (i >> 8) & 1, ks = (i >> 9) & 7, nw = (i >> 12) & 1;
        int n = nw * 32 + h16 * 16 + t * 8 + (lane >> 2);
        int k = ks * 16 + (lane & 3) * 2 + reg * 8 + h;
        int khw = k >> 5, c = k & 31;
        float w = w1[((n * 32 + c) * 2 + (khw >> 1)) * 2 + (khw & 1)];
        g_B1f[i] = __float2half_rn(w);
    }
    for (int i = t0; i < 32768; i += stride) {
        int h = i & 1, reg = (i >> 1) & 1, t = (i >> 2) & 1, lane = (i >> 3) & 31;
        int h16 = (i >> 8) & 1, ks = (i >> 9) & 15, nw = (i >> 13) & 1, nh = (i >> 14) & 1;
        int n = nh * 64 + nw * 32 + h16 * 16 + t * 8 + (lane >> 2);
        int k = ks * 16 + (lane & 3) * 2 + reg * 8 + h;
        int khw = k >> 6, c = k & 63;
        float w = w2[((n * 64 + c) * 2 + (khw >> 1)) * 2 + (khw & 1)];
        g_B2f[i] = __float2half_rn(w);
    }
}

// ---------------- stats0: S and C (patch second moments) over padded x ----------------
__global__ void __launch_bounds__(256) stats0_k(const float* __restrict__ x) {
    __shared__ float sx[900];
    __shared__ float sred[8][54];
    int tid = threadIdx.x, wid = tid >> 5, lid = tid & 31;
    float acc[54];
#pragma unroll
    for (int i = 0; i < 54; i++) acc[i] = 0.f;
    int b0 = blockIdx.x * 16;
    for (int im = 0; im < 16; im++) {
        __syncthreads();
        for (int i = tid; i < 900; i += 256) sx[i] = 0.f;
        __syncthreads();
        const float* xb = x + (size_t)(b0 + im) * 784;
        for (int i = tid; i < 784; i += 256) {
            int r = i / 28, cc = i - r * 28;
            sx[(r + 1) * 30 + cc + 1] = xb[i];
        }
        __syncthreads();
        for (int pix = tid; pix < 784; pix += 256) {
            int oh = pix / 28, ow = pix - oh * 28;
            const float* s = &sx[oh * 30 + ow];
            float p[9] = {s[0], s[1], s[2], s[30], s[31], s[32], s[60], s[61], s[62]};
            int idx = 9;
#pragma unroll
            for (int j = 0; j < 9; j++) {
                acc[j] += p[j];
#pragma unroll
                for (int k = j; k < 9; k++) acc[idx++] += p[j] * p[k];
            }
        }
    }
#pragma unroll
    for (int i = 0; i < 54; i++) {
        float v = acc[i];
#pragma unroll
        for (int o = 16; o >= 1; o >>= 1) v += __shfl_down_sync(0xFFFFFFFFu, v, o);
        if (lid == 0) sred[wid][i] = v;
    }
    __syncthreads();
    if (tid < 54) {
        float v = 0.f;
#pragma unroll
        for (int w = 0; w < 8; w++) v += sred[w][tid];
        atomicAdd(&g_xstat[tid], (double)v);
    }
}

// ---------------- scale kernels ----------------
__global__ void scale0_k(const float* __restrict__ w0, const float* __restrict__ g,
                         const float* __restrict__ be) {
    int c = threadIdx.x;
    double w[9];
#pragma unroll
    for (int j = 0; j < 9; j++) w[j] = (double)w0[c * 9 + j];
    double S = 0.0, Q = 0.0;
#pragma unroll
    for (int j = 0; j < 9; j++) S += w[j] * g_xstat[j];
    int idx = 9;
#pragma unroll
    for (int j = 0; j < 9; j++)
#pragma unroll
        for (int k = j; k < 9; k++) {
            double cv = g_xstat[idx++];
            Q += (j == k ? 1.0 : 2.0) * w[j] * w[k] * cv;
        }
    const double invN = 1.0 / 6422528.0;
    double mean = S * invN;
    double var  = Q * invN - mean * mean;
    double s = (double)g[c] / sqrt(var + 1e-5);
    g_s0[c] = (float)s; g_t0[c] = (float)((double)be[c] - mean * s);
}
__global__ void scale1_k(const float* __restrict__ g, const float* __restrict__ be) {
    int c = threadIdx.x;
    const double invN = 1.0 / 1605632.0;
    double mean = g_stats[64 + c] * invN;
    double var  = g_stats[128 + c] * invN - mean * mean;
    double s = (double)g[c] / sqrt(var + 1e-5);
    g_s1[c] = (float)s; g_t1[c] = (float)((double)be[c] - mean * s);
}
__global__ void scale2_k(const float* __restrict__ g, const float* __restrict__ be) {
    int c = threadIdx.x;
    const double invN = 1.0 / 401408.0;
    double mean = g_stats[192 + c] * invN;
    double var  = g_stats[320 + c] * invN - mean * mean;
    double s = (double)g[c] / sqrt(var + 1e-5);
    g_s2[c] = (float)s; g_t2[c] = (float)((double)be[c] - mean * s);
}

// ======================= conv1 (FUSED conv0): HMMA GEMM  M=1605632(x128), N=64, K=128 ==========
// A tile recomputed from x in-CTA: conv0 fp32 + BN0 + ReLU -> fp16 smem. No y0 tensor.
#define A1STR 136
#define A1STEP (16 * A1STR * 2)
__global__ void __launch_bounds__(256, 3) conv1_k(const float* __restrict__ x,
                                                  const float* __restrict__ w0) {
    __shared__ __align__(16) __half Ab[128 * A1STR];
    __shared__ float s_red[128];
    __shared__ float sx[2][900];
    int tid = threadIdx.x, wid = tid >> 5, lid = tid & 31;
    size_t m0 = (size_t)blockIdx.x * 128;
    int b0 = (int)(m0 / 196);
    int b1 = (int)((m0 + 127) / 196);
    int nimg = b1 - b0 + 1;
    for (int i = tid; i < 1800; i += 256) ((float*)sx)[i] = 0.f;
    if (tid < 128) s_red[tid] = 0.f;
    __syncthreads();
    for (int i = tid; i < nimg * 784; i += 256) {
        int img = i / 784, pix = i - img * 784;
        int r = pix / 28, cc = pix - r * 28;
        sx[img][(r + 1) * 30 + cc + 1] = x[(size_t)(b0 + img) * 784 + pix];
    }
    float w[9];
#pragma unroll
    for (int j = 0; j < 9; j++) w[j] = w0[lid * 9 + j];
    float s0 = g_s0[lid], t0 = g_t0[lid];
    __syncthreads();
    // A fill: warp wid handles rows wid, wid+8, ... ; lane = channel
#pragma unroll
    for (int j = 0; j < 16; j++) {
        int r = wid + j * 8;
        size_t mm = m0 + r;
        int bb = (int)(mm / 196);
        int pix = (int)(mm - (size_t)bb * 196);
        int oh = pix / 14, ow = pix - oh * 14;
        const float* pbase = &sx[bb - b0][(2 * oh) * 30 + 2 * ow];
        float xp[16];
#pragma unroll
        for (int ii = 0; ii < 4; ii++)
#pragma unroll
            for (int jj = 0; jj < 4; jj++) xp[ii * 4 + jj] = pbase[ii * 30 + jj];
#pragma unroll
        for (int khw = 0; khw < 4; khw++) {
            int di = khw >> 1, dj = khw & 1;
            float a = 0.f;
#pragma unroll
            for (int ki = 0; ki < 3; ki++)
#pragma unroll
                for (int kj = 0; kj < 3; kj++)
                    a = fmaf(w[ki * 3 + kj], xp[(di + ki) * 4 + dj + kj], a);
            float v = fmaxf(fmaf(a, s0, t0), 0.f);
            Ab[r * A1STR + khw * 32 + lid] = __float2half_rn(v);
        }
    }
    __syncthreads();

    int mw = wid & 3, nw = wid >> 2;
    int mb = mw * 32, nb = nw * 32;
    float acc[2][4][4];
#pragma unroll
    for (int i = 0; i < 2; i++)
#pragma unroll
        for (int j = 0; j < 4; j++)
#pragma unroll
            for (int q = 0; q < 4; q++) acc[i][j][q] = 0.f;
    const uint4* Bf = (const uint4*)g_B1f;
    uint32_t aB = s2u(&Ab[(mb + (lid & 15)) * A1STR + (lid >> 4) * 8]);
#pragma unroll
    for (int ks = 0; ks < 8; ks++) {
        int base = ((nw * 8 + ks) * 2) * 32 + lid;   // dense hi-only fragments
        uint4 b0v = Bf[base], b1v = Bf[base + 32];
        uint32_t a[2][4];
#pragma unroll
        for (int mt = 0; mt < 2; mt++) ldm4(a[mt], aB + mt * A1STEP + ks * 32);
#pragma unroll
        for (int mt = 0; mt < 2; mt++) {
            mmaf16(acc[mt][0], a[mt], b0v.x, b0v.y);
            mmaf16(acc[mt][1], a[mt], b0v.z, b0v.w);
            mmaf16(acc[mt][2], a[mt], b1v.x, b1v.y);
            mmaf16(acc[mt][3], a[mt], b1v.z, b1v.w);
        }
    }
    __syncthreads();   // A done -> staging (stride 72)

    __half* st = (__half*)Ab;
#pragma unroll
    for (int mt = 0; mt < 2; mt++) {
        int g = mb + mt * 16 + (lid >> 2);
#pragma unroll
        for (int nt = 0; nt < 4; nt++) {
            int col = nb + nt * 8 + (lid & 3) * 2;
            *(__half2*)(st + g * 72 + col)       = __float22half2_rn(make_float2(acc[mt][nt][0], acc[mt][nt][1]));
            *(__half2*)(st + (g + 8) * 72 + col) = __float22half2_rn(make_float2(acc[mt][nt][2], acc[mt][nt][3]));
        }
    }
#pragma unroll
    for (int nt = 0; nt < 4; nt++)
#pragma unroll
        for (int j = 0; j < 2; j++) {
            float v = 0.f, q = 0.f;
#pragma unroll
            for (int mt = 0; mt < 2; mt++) {
                float a = acc[mt][nt][j], b = acc[mt][nt][j + 2];
                v += a + b;
                q = fmaf(a, a, q); q = fmaf(b, b, q);
            }
            red4(v); red4(q);
            if (lid < 4) {
                int col = nb + nt * 8 + lid * 2 + j;
                atomicAdd(&s_red[col], v);
                atomicAdd(&s_red[64 + col], q);
            }
        }
    __syncthreads();
    {   // y1 write (permuted rows), 2 threads per row, 64B each
        int r = tid >> 1, h = tid & 1;
        size_t mm = m0 + r;
        int bb = (int)(mm / 196);
        int rem = (int)(mm - (size_t)bb * 196);
        int OH = rem / 14, OW = rem - OH * 14;
        __half* dst = g_y1h + (((size_t)bb * 7 + (OH >> 1)) * 7 + (OW >> 1)) * 256 +
                      ((((OH & 1) << 1) | (OW & 1)) << 6) + h * 32;
        const __half* srow = st + r * 72 + h * 32;
#pragma unroll
        for (int q = 0; q < 4; q++) ((uint4*)dst)[q] = ((const uint4*)srow)[q];
    }
    if (tid < 64) {
        atomicAdd(&g_stats[64 + tid], (double)s_red[tid]);
        atomicAdd(&g_stats[128 + tid], (double)s_red[64 + tid]);
    }
}

// ======================= conv2: HMMA GEMM  M=401408(x128), N=128(2x64), K=256 =======================
#define A2STR 264
#define A2STEP (16 * A2STR * 2)
#define SM2_BYTES (128 * A2STR * 2 + 512)
__global__ void __launch_bounds__(256, 3) conv2_k() {
    extern __shared__ __align__(16) __half Ab2[];
    float* s_red = (float*)(Ab2 + 128 * A2STR);
    int tid = threadIdx.x, wid = tid >> 5, lid = tid & 31;
    size_t m0 = (size_t)blockIdx.x * 128;
    int nh = blockIdx.y;
    const __half* Asrc = g_y1h + m0 * 256;
#pragma unroll
    for (int i = 0; i < 16; i++) {
        int idx = tid + i * 256;
        int row = idx >> 5, c16 = idx & 31;
        cpasync16(s2u(&Ab2[row * A2STR + c16 * 8]), Asrc + row * 256 + c16 * 8);
    }
    CP_COMMIT;
    if (tid < 128) s_red[tid] = 0.f;
    // packed BN1 scales + hoisted shuffles (4 variants)
    uint32_t spk, tpk;
    { __half2 sp = __floats2half2_rn(g_s1[2 * lid], g_s1[2 * lid + 1]);
      __half2 tp = __floats2half2_rn(g_t1[2 * lid], g_t1[2 * lid + 1]);
      spk = *(uint32_t*)&sp; tpk = *(uint32_t*)&tp; }
    uint32_t sc0[4], tc0[4], sc8[4], tc8[4];
#pragma unroll
    for (int v = 0; v < 4; v++) {
        int i0 = v * 8 + (lid & 3);
        sc0[v] = __shfl_sync(0xFFFFFFFFu, spk, i0);     tc0[v] = __shfl_sync(0xFFFFFFFFu, tpk, i0);
        sc8[v] = __shfl_sync(0xFFFFFFFFu, spk, i0 + 4); tc8[v] = __shfl_sync(0xFFFFFFFFu, tpk, i0 + 4);
    }
    int mw = wid & 3, nw = wid >> 2;
    int mb = mw * 32, nb = nw * 32;
    float acc[2][4][4];
#pragma unroll
    for (int i = 0; i < 2; i++)
#pragma unroll
        for (int j = 0; j < 4; j++)
#pragma unroll
            for (int q = 0; q < 4; q++) acc[i][j][q] = 0.f;
    const uint4* Bf = (const uint4*)g_B2f;
    uint32_t aB = s2u(&Ab2[(mb + (lid & 15)) * A2STR + (lid >> 4) * 8]);
    CP_WAIT0;
    __syncthreads();
#pragma unroll
    for (int ks = 0; ks < 16; ks++) {
        int base = ((((nh * 2 + nw) * 16) + ks) * 2) * 32 + lid;
        uint4 b0 = Bf[base], b1 = Bf[base + 32];
        uint32_t a[2][4];
#pragma unroll
        for (int mt = 0; mt < 2; mt++) ldm4(a[mt], aB + mt * A2STEP + ks * 32);
        int p = ks & 3;
        __half2 s0v = H2(sc0[p]), t0v = H2(tc0[p]), s8v = H2(sc8[p]), t8v = H2(tc8[p]);
#pragma unroll
        for (int mt = 0; mt < 2; mt++) {
            H2(a[mt][0]) = __hfma2_relu(H2(a[mt][0]), s0v, t0v);
            H2(a[mt][1]) = __hfma2_relu(H2(a[mt][1]), s0v, t0v);
            H2(a[mt][2]) = __hfma2_relu(H2(a[mt][2]), s8v, t8v);
            H2(a[mt][3]) = __hfma2_relu(H2(a[mt][3]), s8v, t8v);
        }
#pragma unroll
        for (int mt = 0; mt < 2; mt++) {
            mmaf16(acc[mt][0], a[mt], b0.x, b0.y);
            mmaf16(acc[mt][1], a[mt], b0.z, b0.w);
            mmaf16(acc[mt][2], a[mt], b1.x, b1.y);
            mmaf16(acc[mt][3], a[mt], b1.z, b1.w);
        }
    }
    __syncthreads();

    __half* st = (__half*)Ab2;   // staging stride 72
#pragma unroll
    for (int mt = 0; mt < 2; mt++) {
        int g = mb + mt * 16 + (lid >> 2);
#pragma unroll
        for (int nt = 0; nt < 4; nt++) {
            int col = nb + nt * 8 + (lid & 3) * 2;
            *(__half2*)(st + g * 72 + col)       = __float22half2_rn(make_float2(acc[mt][nt][0], acc[mt][nt][1]));
            *(__half2*)(st + (g + 8) * 72 + col) = __float22half2_rn(make_float2(acc[mt][nt][2], acc[mt][nt][3]));
        }
    }
#pragma unroll
    for (int nt = 0; nt < 4; nt++)
#pragma unroll
        for (int j = 0; j < 2; j++) {
            float v = 0.f, q = 0.f;
#pragma unroll
            for (int mt = 0; mt < 2; mt++) {
                float a = acc[mt][nt][j], b = acc[mt][nt][j + 2];
                v += a + b;
                q = fmaf(a, a, q); q = fmaf(b, b, q);
            }
            red4(v); red4(q);
            if (lid < 4) {
                int col = nb + nt * 8 + lid * 2 + j;
                atomicAdd(&s_red[col], v);
                atomicAdd(&s_red[64 + col], q);
            }
        }
    __syncthreads();
    {   // y2 write row-major, this CTA's 64-col half; 2 threads per row, 64B each
        int r = tid >> 1, h = tid & 1;
        __half* dst = g_y2h + (m0 + r) * 128 + nh * 64 + h * 32;
        const __half* srow = st + r * 72 + h * 32;
#pragma unroll
        for (int q = 0; q < 4; q++) ((uint4*)dst)[q] = ((const uint4*)srow)[q];
    }
    if (tid < 64) {
        atomicAdd(&g_stats[192 + nh * 64 + tid], (double)s_red[tid]);
        atomicAdd(&g_stats[320 + nh * 64 + tid], (double)s_red[64 + tid]);
    }
}

// ---------------- final: BN2+ReLU, avg-pool 49, FC 128->10 ----------------
__global__ void __launch_bounds__(128) final_k(const float* __restrict__ wfc,
                                               const float* __restrict__ bfc,
                                               float* __restrict__ out) {
    __shared__ float f[128];
    int b = blockIdx.x, tid = threadIdx.x;
    const __half* y = g_y2h + (size_t)b * 49 * 128;
    float s = g_s2[tid], t = g_t2[tid];
    float acc = 0.f;
#pragma unroll 7
    for (int p = 0; p < 49; p++) acc += fmaxf(fmaf(__half2float(y[p * 128 + tid]), s, t), 0.f);
    f[tid] = acc * (1.f / 49.f);
    __syncthreads();
    if (tid < 10) {
        float o = bfc[tid];
        const float* wr = wfc + tid * 128;
#pragma unroll 8
        for (int c2 = 0; c2 < 128; c2++) o = fmaf(f[c2], wr[c2], o);
        out[(size_t)b * 10 + tid] = o;
    }
}

// ---------------- launch ----------------
extern "C" void kernel_launch(void* const* d_in, const int* in_sizes, int n_in,
                              void* d_out, int out_size) {
    const float* x   = (const float*)d_in[0];
    const float* w0  = (const float*)d_in[1];
    const float* g0  = (const float*)d_in[3];
    const float* be0 = (const float*)d_in[4];
    const float* w1  = (const float*)d_in[5];
    const float* g1  = (const float*)d_in[7];
    const float* be1 = (const float*)d_in[8];
    const float* w2  = (const float*)d_in[9];
    const float* g2  = (const float*)d_in[11];
    const float* be2 = (const float*)d_in[12];
    const float* wfc = (const float*)d_in[13];
    const float* bfc = (const float*)d_in[14];
    float* out = (float*)d_out;

    cudaFuncSetAttribute(conv2_k, cudaFuncAttributeMaxDynamicSharedMemorySize, SM2_BYTES);

    prep_k<<<128, 256>>>(w1, w2);
    stats0_k<<<512, 256>>>(x);
    scale0_k<<<1, 32>>>(w0, g0, be0);
    conv1_k<<<12544, 256>>>(x, w0);
    scale1_k<<<1, 64>>>(g1, be1);
    conv2_k<<<dim3(3136, 2), 256, SM2_BYTES>>>();
    scale2_k<<<1, 128>>>(g2, be2);
    final_k<<<BATCH, 128>>>(wfc, bfc, out);
}